// round 1
// baseline (speedup 1.0000x reference)
#include <cuda_runtime.h>
#include <cuda_bf16.h>

#define DF 128
#define NMAX 100000
#define GMAX 1024

// persistent scratch (no allocations allowed)
__device__ float g_bufA[(size_t)NMAX * DF];
__device__ float g_bufB[(size_t)NMAX * DF];
__device__ float g_bufC[(size_t)NMAX * DF];
__device__ float g_pool[(size_t)GMAX * DF];

// ---------------------------------------------------------------------------
__global__ void zero_kernel(float4* __restrict__ p, int n4) {
    int i = blockIdx.x * blockDim.x + threadIdx.x;
    if (i < n4) p[i] = make_float4(0.f, 0.f, 0.f, 0.f);
}

// ---------------------------------------------------------------------------
// One warp per edge: gather h[src] row (1 float4/lane), RED-add into agg[dst].
__global__ void edge_kernel(const float* __restrict__ h, const int* __restrict__ src,
                            const int* __restrict__ dst, float* __restrict__ agg, int E) {
    int gw   = (blockIdx.x * blockDim.x + threadIdx.x) >> 5;
    int lane = threadIdx.x & 31;
    if (gw >= E) return;
    int s = __ldg(src + gw);
    int d = __ldg(dst + gw);
    float4 v = *(const float4*)(h + (size_t)s * DF + lane * 4);
    float* p = agg + (size_t)d * DF + lane * 4;
    atomicAdd(p + 0, v.x);
    atomicAdd(p + 1, v.y);
    atomicAdd(p + 2, v.z);
    atomicAdd(p + 3, v.w);
}

// ---------------------------------------------------------------------------
// Fused: out = relu(LN( (x [+ (1+eps)*hres]) @ W + bias ; gamma, beta ))
// W[128][128] in smem (64KB). Block = 256 threads (8 warps), 8 rows/warp,
// 2 row-iterations -> 128 rows/block. Per lane: 4 output cols (lane*4..+3).
__global__ void __launch_bounds__(256, 2)
gemm_ln_relu_kernel(const float* __restrict__ x, const float* __restrict__ hres,
                    const float* __restrict__ epsArr, int layer,
                    const float* __restrict__ W, const float* __restrict__ bias,
                    const float* __restrict__ gamma, const float* __restrict__ beta,
                    float* __restrict__ out, int nrows) {
    extern __shared__ float smem[];
    float4* Ws4 = (float4*)smem;            // 128*32 float4 = 64KB
    float*  xs  = smem + DF * DF;           // 8 warps * 8 rows * 128 = 32KB
    float*  bs  = xs + 8 * 8 * DF;          // 128
    float*  gs  = bs + DF;                  // 128
    float*  es  = gs + DF;                  // 128

    int tid = threadIdx.x;

    const float4* Wg = (const float4*)W;
    #pragma unroll
    for (int i = tid; i < DF * (DF / 4); i += 256) Ws4[i] = Wg[i];
    if (tid < DF) { bs[tid] = bias[tid]; gs[tid] = gamma[tid]; es[tid] = beta[tid]; }
    __syncthreads();

    float escale = (hres != nullptr) ? (1.0f + epsArr[layer]) : 0.0f;

    int warp = tid >> 5, lane = tid & 31;
    float4* xw4 = (float4*)(xs + warp * 8 * DF);   // [8 rows][32 float4]

    for (int iter = 0; iter < 2; ++iter) {
        int rowBase = blockIdx.x * 128 + iter * 64 + warp * 8;

        __syncwarp();
        #pragma unroll
        for (int r = 0; r < 8; ++r) {
            int row = rowBase + r;
            float4 v = make_float4(0.f, 0.f, 0.f, 0.f);
            if (row < nrows) {
                v = *(const float4*)(x + (size_t)row * DF + lane * 4);
                if (hres) {
                    float4 hv = *(const float4*)(hres + (size_t)row * DF + lane * 4);
                    v.x = fmaf(escale, hv.x, v.x);
                    v.y = fmaf(escale, hv.y, v.y);
                    v.z = fmaf(escale, hv.z, v.z);
                    v.w = fmaf(escale, hv.w, v.w);
                }
            }
            xw4[r * 32 + lane] = v;
        }
        __syncwarp();

        float acc[8][4];
        #pragma unroll
        for (int r = 0; r < 8; ++r) {
            acc[r][0] = 0.f; acc[r][1] = 0.f; acc[r][2] = 0.f; acc[r][3] = 0.f;
        }

        #pragma unroll 2
        for (int k4 = 0; k4 < 32; ++k4) {
            float4 w0 = Ws4[(k4 * 4 + 0) * 32 + lane];
            float4 w1 = Ws4[(k4 * 4 + 1) * 32 + lane];
            float4 w2 = Ws4[(k4 * 4 + 2) * 32 + lane];
            float4 w3 = Ws4[(k4 * 4 + 3) * 32 + lane];
            #pragma unroll
            for (int r = 0; r < 8; ++r) {
                float4 xv = xw4[r * 32 + k4];   // warp-broadcast
                acc[r][0] = fmaf(xv.x, w0.x, acc[r][0]);
                acc[r][1] = fmaf(xv.x, w0.y, acc[r][1]);
                acc[r][2] = fmaf(xv.x, w0.z, acc[r][2]);
                acc[r][3] = fmaf(xv.x, w0.w, acc[r][3]);
                acc[r][0] = fmaf(xv.y, w1.x, acc[r][0]);
                acc[r][1] = fmaf(xv.y, w1.y, acc[r][1]);
                acc[r][2] = fmaf(xv.y, w1.z, acc[r][2]);
                acc[r][3] = fmaf(xv.y, w1.w, acc[r][3]);
                acc[r][0] = fmaf(xv.z, w2.x, acc[r][0]);
                acc[r][1] = fmaf(xv.z, w2.y, acc[r][1]);
                acc[r][2] = fmaf(xv.z, w2.z, acc[r][2]);
                acc[r][3] = fmaf(xv.z, w2.w, acc[r][3]);
                acc[r][0] = fmaf(xv.w, w3.x, acc[r][0]);
                acc[r][1] = fmaf(xv.w, w3.y, acc[r][1]);
                acc[r][2] = fmaf(xv.w, w3.z, acc[r][2]);
                acc[r][3] = fmaf(xv.w, w3.w, acc[r][3]);
            }
        }

        float4 b4 = ((const float4*)bs)[lane];
        float4 g4 = ((const float4*)gs)[lane];
        float4 e4 = ((const float4*)es)[lane];

        #pragma unroll
        for (int r = 0; r < 8; ++r) {
            int row = rowBase + r;
            float a0 = acc[r][0] + b4.x;
            float a1 = acc[r][1] + b4.y;
            float a2 = acc[r][2] + b4.z;
            float a3 = acc[r][3] + b4.w;
            float s = a0 + a1 + a2 + a3;
            float q = a0 * a0 + a1 * a1 + a2 * a2 + a3 * a3;
            #pragma unroll
            for (int off = 16; off > 0; off >>= 1) {
                s += __shfl_xor_sync(0xFFFFFFFFu, s, off);
                q += __shfl_xor_sync(0xFFFFFFFFu, q, off);
            }
            float mu   = s * (1.0f / 128.0f);
            float var  = q * (1.0f / 128.0f) - mu * mu;
            float rstd = rsqrtf(var + 1e-5f);
            float4 o;
            o.x = fmaxf(0.f, (a0 - mu) * rstd * g4.x + e4.x);
            o.y = fmaxf(0.f, (a1 - mu) * rstd * g4.y + e4.y);
            o.z = fmaxf(0.f, (a2 - mu) * rstd * g4.z + e4.z);
            o.w = fmaxf(0.f, (a3 - mu) * rstd * g4.w + e4.w);
            if (row < nrows)
                *(float4*)(out + (size_t)row * DF + lane * 4) = o;
        }
    }
}

// ---------------------------------------------------------------------------
// gid is sorted: boundary-flush segment sum. 128 threads (one column each),
// 512 contiguous nodes per block, atomic flush only at graph boundaries.
__global__ void pool_kernel(const float* __restrict__ h, const int* __restrict__ gid,
                            float* __restrict__ pool, int N) {
    int c  = threadIdx.x;
    int n0 = blockIdx.x * 512;
    if (n0 >= N) return;
    int curg = __ldg(gid + n0);
    float acc = 0.f;
    #pragma unroll 4
    for (int i = 0; i < 512; ++i) {
        int n = n0 + i;
        if (n >= N) break;
        int g = __ldg(gid + n);
        if (g != curg) {
            atomicAdd(&pool[(size_t)curg * DF + c], acc);
            acc = 0.f;
            curg = g;
        }
        acc += __ldg(h + (size_t)n * DF + c);
    }
    atomicAdd(&pool[(size_t)curg * DF + c], acc);
}

// ---------------------------------------------------------------------------
// Per-graph head: y = relu(LN(concat(pool,desc) @ fc1W + fc1b)); out = y@fc2W+fc2b
__global__ void head_kernel(const float* __restrict__ pool, const float* __restrict__ desc,
                            const float* __restrict__ fc1W, const float* __restrict__ fc1b,
                            const float* __restrict__ n1g, const float* __restrict__ n1b,
                            const float* __restrict__ fc2W, const float* __restrict__ fc2b,
                            float* __restrict__ out, int X, int C) {
    int g = blockIdx.x;
    int t = threadIdx.x;
    int warp = t >> 5, lane = t & 31;

    __shared__ float xin[DF + 64];
    __shared__ float ss[4], qq[4];

    xin[t] = pool[(size_t)g * DF + t];
    if (t < X) xin[DF + t] = desc[(size_t)g * X + t];
    __syncthreads();

    int K = DF + X;
    float acc = fc1b[t];
    for (int k = 0; k < K; ++k)
        acc = fmaf(xin[k], __ldg(fc1W + (size_t)k * DF + t), acc);

    float s = acc, q = acc * acc;
    #pragma unroll
    for (int off = 16; off > 0; off >>= 1) {
        s += __shfl_xor_sync(0xFFFFFFFFu, s, off);
        q += __shfl_xor_sync(0xFFFFFFFFu, q, off);
    }
    if (lane == 0) { ss[warp] = s; qq[warp] = q; }
    __syncthreads();
    s = ss[0] + ss[1] + ss[2] + ss[3];
    q = qq[0] + qq[1] + qq[2] + qq[3];
    float mu   = s * (1.0f / 128.0f);
    float var  = q * (1.0f / 128.0f) - mu * mu;
    float rstd = rsqrtf(var + 1e-5f);
    float y = fmaxf(0.f, (acc - mu) * rstd * n1g[t] + n1b[t]);

    for (int c = 0; c < C; ++c) {
        float p = y * __ldg(fc2W + (size_t)t * C + c);
        #pragma unroll
        for (int off = 16; off > 0; off >>= 1)
            p += __shfl_xor_sync(0xFFFFFFFFu, p, off);
        __syncthreads();
        if (lane == 0) ss[warp] = p;
        __syncthreads();
        if (t == 0) out[(size_t)g * C + c] = ss[0] + ss[1] + ss[2] + ss[3] + fc2b[c];
    }
}

// ---------------------------------------------------------------------------
extern "C" void kernel_launch(void* const* d_in, const int* in_sizes, int n_in,
                              void* d_out, int out_size) {
    const float* h    = (const float*)d_in[0];
    const float* desc = (const float*)d_in[1];
    const int*   src  = (const int*)d_in[2];
    const int*   dst  = (const int*)d_in[3];
    const int*   gid  = (const int*)d_in[4];
    const float* W1   = (const float*)d_in[5];
    const float* b1   = (const float*)d_in[6];
    const float* g1   = (const float*)d_in[7];
    const float* be1  = (const float*)d_in[8];
    const float* W2   = (const float*)d_in[9];
    const float* b2   = (const float*)d_in[10];
    const float* eps  = (const float*)d_in[11];
    const float* ng   = (const float*)d_in[12];
    const float* nb   = (const float*)d_in[13];
    const float* fc1W = (const float*)d_in[14];
    const float* fc1b = (const float*)d_in[15];
    const float* n1g  = (const float*)d_in[16];
    const float* n1b  = (const float*)d_in[17];
    const float* fc2W = (const float*)d_in[18];
    const float* fc2b = (const float*)d_in[19];
    float* out = (float*)d_out;

    int N = in_sizes[0] / DF;
    int E = in_sizes[2];
    int L = in_sizes[11];
    int X = in_sizes[14] / DF - DF;
    if (X <= 0) X = 16;
    int G = in_sizes[1] / X;
    int C = in_sizes[18] / DF;
    if (C <= 0) C = 1;
    if (N > NMAX) N = NMAX;
    if (G > GMAX) G = GMAX;

    float *bufA, *bufB, *bufC, *pool;
    cudaGetSymbolAddress((void**)&bufA, g_bufA);
    cudaGetSymbolAddress((void**)&bufB, g_bufB);
    cudaGetSymbolAddress((void**)&bufC, g_bufC);
    cudaGetSymbolAddress((void**)&pool, g_pool);

    const int SMEM_BYTES = (DF * DF + 8 * 8 * DF + 3 * DF) * sizeof(float); // 99840
    cudaFuncSetAttribute(gemm_ln_relu_kernel,
                         cudaFuncAttributeMaxDynamicSharedMemorySize, SMEM_BYTES);

    int nd4 = N * (DF / 4);
    int gb  = (N + 127) / 128;

    const float* hcur = h;
    for (int l = 0; l < L; ++l) {
        zero_kernel<<<(nd4 + 255) / 256, 256>>>((float4*)bufA, nd4);
        edge_kernel<<<(E + 7) / 8, 256>>>(hcur, src, dst, bufA, E);
        gemm_ln_relu_kernel<<<gb, 256, SMEM_BYTES>>>(
            bufA, hcur, eps, l,
            W1 + (size_t)l * DF * DF, b1 + (size_t)l * DF,
            g1 + (size_t)l * DF, be1 + (size_t)l * DF, bufB, N);
        gemm_ln_relu_kernel<<<gb, 256, SMEM_BYTES>>>(
            bufB, nullptr, nullptr, 0,
            W2 + (size_t)l * DF * DF, b2 + (size_t)l * DF,
            ng + (size_t)l * DF, nb + (size_t)l * DF, bufC, N);
        hcur = bufC;
    }

    int gd4 = G * (DF / 4);
    zero_kernel<<<(gd4 + 255) / 256, 256>>>((float4*)pool, gd4);
    pool_kernel<<<(N + 511) / 512, 128>>>(hcur, gid, pool, N);
    head_kernel<<<G, 128>>>(pool, desc, fc1W, fc1b, n1g, n1b, fc2W, fc2b, out, X, C);
}

// round 2
// speedup vs baseline: 1.5621x; 1.5621x over previous
#include <cuda_runtime.h>
#include <cuda_bf16.h>

#define DF 128
#define NMAX 100000
#define GMAX 1024

// persistent scratch (no allocations allowed)
__device__ float g_bufA[(size_t)NMAX * DF];
__device__ float g_bufB[(size_t)NMAX * DF];
__device__ float g_bufC[(size_t)NMAX * DF];
__device__ float g_pool[(size_t)GMAX * DF];

// ---------------------------------------------------------------------------
// One warp per edge: gather h[src] row (1 float4/lane), one vector RED into
// agg[dst] per lane (red.global.add.v4.f32, sm_90+).
__global__ void edge_kernel(const float* __restrict__ h, const int* __restrict__ src,
                            const int* __restrict__ dst, float* __restrict__ agg, int E) {
    int gw   = (blockIdx.x * blockDim.x + threadIdx.x) >> 5;
    int lane = threadIdx.x & 31;
    if (gw >= E) return;
    int s = __ldg(src + gw);
    int d = __ldg(dst + gw);
    float4 v = *(const float4*)(h + (size_t)s * DF + lane * 4);
    float* p = agg + (size_t)d * DF + lane * 4;
    asm volatile("red.global.add.v4.f32 [%0], {%1, %2, %3, %4};"
                 :: "l"(p), "f"(v.x), "f"(v.y), "f"(v.z), "f"(v.w)
                 : "memory");
}

// ---------------------------------------------------------------------------
// Fused: out = relu(LN( (x [+ (1+eps)*hres]) @ W + bias ; gamma, beta ))
// W[128][128] in smem (64KB). Block = 256 threads (8 warps), 8 rows/warp,
// 2 row-iterations -> 128 rows/block. Per lane: 4 output cols (lane*4..+3).
__global__ void __launch_bounds__(256, 2)
gemm_ln_relu_kernel(const float* __restrict__ x, const float* __restrict__ hres,
                    const float* __restrict__ epsArr, int layer,
                    const float* __restrict__ W, const float* __restrict__ bias,
                    const float* __restrict__ gamma, const float* __restrict__ beta,
                    float* __restrict__ out, int nrows) {
    extern __shared__ float smem[];
    float4* Ws4 = (float4*)smem;            // 128*32 float4 = 64KB
    float*  xs  = smem + DF * DF;           // 8 warps * 8 rows * 128 = 32KB
    float*  bs  = xs + 8 * 8 * DF;          // 128
    float*  gs  = bs + DF;                  // 128
    float*  es  = gs + DF;                  // 128

    int tid = threadIdx.x;

    const float4* Wg = (const float4*)W;
    #pragma unroll
    for (int i = tid; i < DF * (DF / 4); i += 256) Ws4[i] = Wg[i];
    if (tid < DF) { bs[tid] = bias[tid]; gs[tid] = gamma[tid]; es[tid] = beta[tid]; }
    __syncthreads();

    float escale = (hres != nullptr) ? (1.0f + epsArr[layer]) : 0.0f;

    int warp = tid >> 5, lane = tid & 31;
    float4* xw4 = (float4*)(xs + warp * 8 * DF);   // [8 rows][32 float4]

    for (int iter = 0; iter < 2; ++iter) {
        int rowBase = blockIdx.x * 128 + iter * 64 + warp * 8;

        __syncwarp();
        #pragma unroll
        for (int r = 0; r < 8; ++r) {
            int row = rowBase + r;
            float4 v = make_float4(0.f, 0.f, 0.f, 0.f);
            if (row < nrows) {
                v = *(const float4*)(x + (size_t)row * DF + lane * 4);
                if (hres) {
                    float4 hv = *(const float4*)(hres + (size_t)row * DF + lane * 4);
                    v.x = fmaf(escale, hv.x, v.x);
                    v.y = fmaf(escale, hv.y, v.y);
                    v.z = fmaf(escale, hv.z, v.z);
                    v.w = fmaf(escale, hv.w, v.w);
                }
            }
            xw4[r * 32 + lane] = v;
        }
        __syncwarp();

        float acc[8][4];
        #pragma unroll
        for (int r = 0; r < 8; ++r) {
            acc[r][0] = 0.f; acc[r][1] = 0.f; acc[r][2] = 0.f; acc[r][3] = 0.f;
        }

        #pragma unroll 2
        for (int k4 = 0; k4 < 32; ++k4) {
            float4 w0 = Ws4[(k4 * 4 + 0) * 32 + lane];
            float4 w1 = Ws4[(k4 * 4 + 1) * 32 + lane];
            float4 w2 = Ws4[(k4 * 4 + 2) * 32 + lane];
            float4 w3 = Ws4[(k4 * 4 + 3) * 32 + lane];
            #pragma unroll
            for (int r = 0; r < 8; ++r) {
                float4 xv = xw4[r * 32 + k4];   // warp-broadcast
                acc[r][0] = fmaf(xv.x, w0.x, acc[r][0]);
                acc[r][1] = fmaf(xv.x, w0.y, acc[r][1]);
                acc[r][2] = fmaf(xv.x, w0.z, acc[r][2]);
                acc[r][3] = fmaf(xv.x, w0.w, acc[r][3]);
                acc[r][0] = fmaf(xv.y, w1.x, acc[r][0]);
                acc[r][1] = fmaf(xv.y, w1.y, acc[r][1]);
                acc[r][2] = fmaf(xv.y, w1.z, acc[r][2]);
                acc[r][3] = fmaf(xv.y, w1.w, acc[r][3]);
                acc[r][0] = fmaf(xv.z, w2.x, acc[r][0]);
                acc[r][1] = fmaf(xv.z, w2.y, acc[r][1]);
                acc[r][2] = fmaf(xv.z, w2.z, acc[r][2]);
                acc[r][3] = fmaf(xv.z, w2.w, acc[r][3]);
                acc[r][0] = fmaf(xv.w, w3.x, acc[r][0]);
                acc[r][1] = fmaf(xv.w, w3.y, acc[r][1]);
                acc[r][2] = fmaf(xv.w, w3.z, acc[r][2]);
                acc[r][3] = fmaf(xv.w, w3.w, acc[r][3]);
            }
        }

        float4 b4 = ((const float4*)bs)[lane];
        float4 g4 = ((const float4*)gs)[lane];
        float4 e4 = ((const float4*)es)[lane];

        #pragma unroll
        for (int r = 0; r < 8; ++r) {
            int row = rowBase + r;
            float a0 = acc[r][0] + b4.x;
            float a1 = acc[r][1] + b4.y;
            float a2 = acc[r][2] + b4.z;
            float a3 = acc[r][3] + b4.w;
            float s = a0 + a1 + a2 + a3;
            float q = a0 * a0 + a1 * a1 + a2 * a2 + a3 * a3;
            #pragma unroll
            for (int off = 16; off > 0; off >>= 1) {
                s += __shfl_xor_sync(0xFFFFFFFFu, s, off);
                q += __shfl_xor_sync(0xFFFFFFFFu, q, off);
            }
            float mu   = s * (1.0f / 128.0f);
            float var  = q * (1.0f / 128.0f) - mu * mu;
            float rstd = rsqrtf(var + 1e-5f);
            float4 o;
            o.x = fmaxf(0.f, (a0 - mu) * rstd * g4.x + e4.x);
            o.y = fmaxf(0.f, (a1 - mu) * rstd * g4.y + e4.y);
            o.z = fmaxf(0.f, (a2 - mu) * rstd * g4.z + e4.z);
            o.w = fmaxf(0.f, (a3 - mu) * rstd * g4.w + e4.w);
            if (row < nrows)
                *(float4*)(out + (size_t)row * DF + lane * 4) = o;
        }
    }
}

// ---------------------------------------------------------------------------
// gid is sorted: boundary-flush segment sum. 128 threads (one column each),
// 512 contiguous nodes per block, atomic flush only at graph boundaries.
__global__ void pool_kernel(const float* __restrict__ h, const int* __restrict__ gid,
                            float* __restrict__ pool, int N) {
    int c  = threadIdx.x;
    int n0 = blockIdx.x * 512;
    if (n0 >= N) return;
    int curg = __ldg(gid + n0);
    float acc = 0.f;
    #pragma unroll 4
    for (int i = 0; i < 512; ++i) {
        int n = n0 + i;
        if (n >= N) break;
        int g = __ldg(gid + n);
        if (g != curg) {
            atomicAdd(&pool[(size_t)curg * DF + c], acc);
            acc = 0.f;
            curg = g;
        }
        acc += __ldg(h + (size_t)n * DF + c);
    }
    atomicAdd(&pool[(size_t)curg * DF + c], acc);
}

// ---------------------------------------------------------------------------
// Per-graph head: y = relu(LN(concat(pool,desc) @ fc1W + fc1b)); out = y@fc2W+fc2b
__global__ void head_kernel(const float* __restrict__ pool, const float* __restrict__ desc,
                            const float* __restrict__ fc1W, const float* __restrict__ fc1b,
                            const float* __restrict__ n1g, const float* __restrict__ n1b,
                            const float* __restrict__ fc2W, const float* __restrict__ fc2b,
                            float* __restrict__ out, int X, int C) {
    int g = blockIdx.x;
    int t = threadIdx.x;
    int warp = t >> 5, lane = t & 31;

    __shared__ float xin[DF + 64];
    __shared__ float ss[4], qq[4];

    xin[t] = pool[(size_t)g * DF + t];
    if (t < X) xin[DF + t] = desc[(size_t)g * X + t];
    __syncthreads();

    int K = DF + X;
    float acc = fc1b[t];
    for (int k = 0; k < K; ++k)
        acc = fmaf(xin[k], __ldg(fc1W + (size_t)k * DF + t), acc);

    float s = acc, q = acc * acc;
    #pragma unroll
    for (int off = 16; off > 0; off >>= 1) {
        s += __shfl_xor_sync(0xFFFFFFFFu, s, off);
        q += __shfl_xor_sync(0xFFFFFFFFu, q, off);
    }
    if (lane == 0) { ss[warp] = s; qq[warp] = q; }
    __syncthreads();
    s = ss[0] + ss[1] + ss[2] + ss[3];
    q = qq[0] + qq[1] + qq[2] + qq[3];
    float mu   = s * (1.0f / 128.0f);
    float var  = q * (1.0f / 128.0f) - mu * mu;
    float rstd = rsqrtf(var + 1e-5f);
    float y = fmaxf(0.f, (acc - mu) * rstd * n1g[t] + n1b[t]);

    for (int c = 0; c < C; ++c) {
        float p = y * __ldg(fc2W + (size_t)t * C + c);
        #pragma unroll
        for (int off = 16; off > 0; off >>= 1)
            p += __shfl_xor_sync(0xFFFFFFFFu, p, off);
        __syncthreads();
        if (lane == 0) ss[warp] = p;
        __syncthreads();
        if (t == 0) out[(size_t)g * C + c] = ss[0] + ss[1] + ss[2] + ss[3] + fc2b[c];
    }
}

// ---------------------------------------------------------------------------
extern "C" void kernel_launch(void* const* d_in, const int* in_sizes, int n_in,
                              void* d_out, int out_size) {
    const float* h    = (const float*)d_in[0];
    const float* desc = (const float*)d_in[1];
    const int*   src  = (const int*)d_in[2];
    const int*   dst  = (const int*)d_in[3];
    const int*   gid  = (const int*)d_in[4];
    const float* W1   = (const float*)d_in[5];
    const float* b1   = (const float*)d_in[6];
    const float* g1   = (const float*)d_in[7];
    const float* be1  = (const float*)d_in[8];
    const float* W2   = (const float*)d_in[9];
    const float* b2   = (const float*)d_in[10];
    const float* eps  = (const float*)d_in[11];
    const float* ng   = (const float*)d_in[12];
    const float* nb   = (const float*)d_in[13];
    const float* fc1W = (const float*)d_in[14];
    const float* fc1b = (const float*)d_in[15];
    const float* n1g  = (const float*)d_in[16];
    const float* n1b  = (const float*)d_in[17];
    const float* fc2W = (const float*)d_in[18];
    const float* fc2b = (const float*)d_in[19];
    float* out = (float*)d_out;

    int N = in_sizes[0] / DF;
    int E = in_sizes[2];
    int L = in_sizes[11];
    int X = in_sizes[14] / DF - DF;
    if (X <= 0) X = 16;
    int G = in_sizes[1] / X;
    int C = in_sizes[18] / DF;
    if (C <= 0) C = 1;
    if (N > NMAX) N = NMAX;
    if (G > GMAX) G = GMAX;

    float *bufA, *bufB, *bufC, *pool;
    cudaGetSymbolAddress((void**)&bufA, g_bufA);
    cudaGetSymbolAddress((void**)&bufB, g_bufB);
    cudaGetSymbolAddress((void**)&bufC, g_bufC);
    cudaGetSymbolAddress((void**)&pool, g_pool);

    const int SMEM_BYTES = (DF * DF + 8 * 8 * DF + 3 * DF) * sizeof(float); // 99840
    cudaFuncSetAttribute(gemm_ln_relu_kernel,
                         cudaFuncAttributeMaxDynamicSharedMemorySize, SMEM_BYTES);

    int gb = (N + 127) / 128;

    const float* hcur = h;
    for (int l = 0; l < L; ++l) {
        cudaMemsetAsync(bufA, 0, (size_t)N * DF * sizeof(float));
        edge_kernel<<<(E + 7) / 8, 256>>>(hcur, src, dst, bufA, E);
        gemm_ln_relu_kernel<<<gb, 256, SMEM_BYTES>>>(
            bufA, hcur, eps, l,
            W1 + (size_t)l * DF * DF, b1 + (size_t)l * DF,
            g1 + (size_t)l * DF, be1 + (size_t)l * DF, bufB, N);
        gemm_ln_relu_kernel<<<gb, 256, SMEM_BYTES>>>(
            bufB, nullptr, nullptr, 0,
            W2 + (size_t)l * DF * DF, b2 + (size_t)l * DF,
            ng + (size_t)l * DF, nb + (size_t)l * DF, bufC, N);
        hcur = bufC;
    }

    cudaMemsetAsync(pool, 0, (size_t)G * DF * sizeof(float));
    pool_kernel<<<(N + 511) / 512, 128>>>(hcur, gid, pool, N);
    head_kernel<<<G, 128>>>(pool, desc, fc1W, fc1b, n1g, n1b, fc2W, fc2b, out, X, C);
}

// round 3
// speedup vs baseline: 1.9406x; 1.2423x over previous
#include <cuda_runtime.h>
#include <cuda_bf16.h>
#include <cstdint>

#define DF 128
#define NMAX 100000
#define GMAX 1024

// persistent scratch (no allocations allowed)
__device__ float g_bufA[(size_t)NMAX * DF];
__device__ float g_bufB[(size_t)NMAX * DF];
__device__ float g_bufC[(size_t)NMAX * DF];
__device__ float g_pool[(size_t)GMAX * DF];

__device__ __forceinline__ float to_tf32(float f) {
    float o;
    asm("cvt.rna.tf32.f32 %0, %1;" : "=f"(o) : "f"(f));
    return o;
}

// ---------------------------------------------------------------------------
// 4 edges per warp: issue all 4 gathers (MLP=4), then 4 vector REDs.
__global__ void edge_kernel(const float* __restrict__ h, const int* __restrict__ src,
                            const int* __restrict__ dst, float* __restrict__ agg, int E) {
    int gw   = (blockIdx.x * blockDim.x + threadIdx.x) >> 5;
    int lane = threadIdx.x & 31;
    int base = gw * 4;
    if (base >= E) return;
    int nE = E - base; if (nE > 4) nE = 4;

    int s[4], d[4];
    #pragma unroll
    for (int i = 0; i < 4; ++i) {
        if (i < nE) { s[i] = __ldg(src + base + i); d[i] = __ldg(dst + base + i); }
    }
    float4 v[4];
    #pragma unroll
    for (int i = 0; i < 4; ++i) {
        if (i < nE) v[i] = *(const float4*)(h + (size_t)s[i] * DF + lane * 4);
    }
    #pragma unroll
    for (int i = 0; i < 4; ++i) {
        if (i < nE) {
            float* p = agg + (size_t)d[i] * DF + lane * 4;
            asm volatile("red.global.add.v4.f32 [%0], {%1, %2, %3, %4};"
                         :: "l"(p), "f"(v[i].x), "f"(v[i].y), "f"(v[i].z), "f"(v[i].w)
                         : "memory");
        }
    }
}

// ---------------------------------------------------------------------------
// tf32 tensor-core GEMM, fused residual + bias + LayerNorm + ReLU.
// CTA tile: 64 rows x 128 cols, K=128. 8 warps, warp tile 16x64 via
// mma.sync.m16n8k8 (rows: (warp&3)*16, cols: (warp>>2)*64).
// K is staged interleaved so (k, k+4) fragment pairs are adjacent -> LDS.64.
// Epilogue: acc -> smem (Cs reuses Xs) -> per-row LN/ReLU -> gmem.
__global__ void __launch_bounds__(256, 2)
gemm_tf32_ln_relu(const float* __restrict__ x, const float* __restrict__ hres,
                  const float* __restrict__ epsArr, int layer,
                  const float* __restrict__ W, const float* __restrict__ bias,
                  const float* __restrict__ gamma, const float* __restrict__ beta,
                  float* __restrict__ out, int nrows) {
    extern __shared__ float smem[];
    float* Ws = smem;                  // [16 ksteps][128 n][8 kk] = 16384 floats (64KB)
    float* Xs = smem + 16384;          // [64 rows][136] = 8704 floats (also Cs)
    float* bs = Xs + 8704;             // 128
    float* gs = bs + DF;               // 128
    float* es = gs + DF;               // 128

    int tid  = threadIdx.x;
    int lane = tid & 31, warp = tid >> 5;

    // Stage W: Ws[(s*128 + n)*8 + kk] = tf32(W[(8s + kphys)*128 + n]),
    // kphys = kk/2 + (kk&1)*4 -> pairs (c, c+4) adjacent.
    for (int idx = tid; idx < 16384; idx += 256) {
        int n   = idx & 127;
        int skk = idx >> 7;
        int s   = skk >> 3, kk = skk & 7;
        int c   = kk >> 1;
        int kphys = (kk & 1) ? (c + 4) : c;
        Ws[((s * 128 + n) << 3) + kk] = to_tf32(W[(size_t)(8 * s + kphys) * DF + n]);
    }
    if (tid < DF) { bs[tid] = bias[tid]; gs[tid] = gamma[tid]; es[tid] = beta[tid]; }

    float escale = (hres != nullptr) ? (1.0f + epsArr[layer]) : 0.0f;
    int rowBlk = blockIdx.x * 64;

    // Stage X (+ residual): Xs[r*136 + s*8 + kk(kcol)]
    for (int idx = tid; idx < 64 * DF; idx += 256) {
        int r = idx >> 7, kcol = idx & 127;
        int row = rowBlk + r;
        float v = 0.f;
        if (row < nrows) {
            v = x[(size_t)row * DF + kcol];
            if (hres) v = fmaf(escale, hres[(size_t)row * DF + kcol], v);
        }
        int s = kcol >> 3, c = kcol & 7;
        int kk = (c < 4) ? (2 * c) : (2 * (c - 4) + 1);
        Xs[r * 136 + s * 8 + kk] = to_tf32(v);
    }
    __syncthreads();

    int wr = (warp & 3) * 16;      // warp row base within tile
    int wc = (warp >> 2) * 64;     // warp col base
    int fr = lane >> 2;            // fragment row/col group 0..7
    int c2 = (lane & 3) * 2;       // interleaved k offset

    float acc[8][4];
    #pragma unroll
    for (int j = 0; j < 8; ++j) {
        acc[j][0] = 0.f; acc[j][1] = 0.f; acc[j][2] = 0.f; acc[j][3] = 0.f;
    }

    #pragma unroll
    for (int s = 0; s < 16; ++s) {
        const float* xp = &Xs[(wr + fr) * 136 + s * 8 + c2];
        float2 alo = *(const float2*)xp;              // (k=c, k=c+4) row fr
        float2 ahi = *(const float2*)(xp + 8 * 136);  // row fr+8
        uint32_t a0 = __float_as_uint(alo.x), a2 = __float_as_uint(alo.y);
        uint32_t a1 = __float_as_uint(ahi.x), a3 = __float_as_uint(ahi.y);

        const float* wp = &Ws[((s * 128) + wc + fr) * 8 + c2];
        float2 bv[8];
        #pragma unroll
        for (int j = 0; j < 8; ++j) bv[j] = *(const float2*)(wp + j * 64);

        #pragma unroll
        for (int j = 0; j < 8; ++j) {
            uint32_t b0 = __float_as_uint(bv[j].x), b1 = __float_as_uint(bv[j].y);
            asm volatile(
                "mma.sync.aligned.m16n8k8.row.col.f32.tf32.tf32.f32 "
                "{%0,%1,%2,%3}, {%4,%5,%6,%7}, {%8,%9}, {%0,%1,%2,%3};"
                : "+f"(acc[j][0]), "+f"(acc[j][1]), "+f"(acc[j][2]), "+f"(acc[j][3])
                : "r"(a0), "r"(a1), "r"(a2), "r"(a3), "r"(b0), "r"(b1));
        }
    }

    __syncthreads();   // Xs -> Cs reuse
    float* Cs = Xs;
    #pragma unroll
    for (int j = 0; j < 8; ++j) {
        int n = wc + j * 8 + c2;
        *(float2*)&Cs[(wr + fr) * 136 + n]     = make_float2(acc[j][0], acc[j][1]);
        *(float2*)&Cs[(wr + fr + 8) * 136 + n] = make_float2(acc[j][2], acc[j][3]);
    }
    __syncthreads();

    // LN + ReLU: each warp handles 8 rows, lane owns 4 cols.
    float4 b4 = ((const float4*)bs)[lane];
    float4 g4 = ((const float4*)gs)[lane];
    float4 e4 = ((const float4*)es)[lane];
    #pragma unroll
    for (int rr = 0; rr < 8; ++rr) {
        int lrow = warp * 8 + rr;
        int grow = rowBlk + lrow;
        float4 a = *(const float4*)&Cs[lrow * 136 + lane * 4];
        float a0 = a.x + b4.x, a1 = a.y + b4.y, a2 = a.z + b4.z, a3 = a.w + b4.w;
        float s = a0 + a1 + a2 + a3;
        float q = a0 * a0 + a1 * a1 + a2 * a2 + a3 * a3;
        #pragma unroll
        for (int off = 16; off > 0; off >>= 1) {
            s += __shfl_xor_sync(0xFFFFFFFFu, s, off);
            q += __shfl_xor_sync(0xFFFFFFFFu, q, off);
        }
        float mu   = s * (1.0f / 128.0f);
        float var  = q * (1.0f / 128.0f) - mu * mu;
        float rstd = rsqrtf(var + 1e-5f);
        float4 o;
        o.x = fmaxf(0.f, (a0 - mu) * rstd * g4.x + e4.x);
        o.y = fmaxf(0.f, (a1 - mu) * rstd * g4.y + e4.y);
        o.z = fmaxf(0.f, (a2 - mu) * rstd * g4.z + e4.z);
        o.w = fmaxf(0.f, (a3 - mu) * rstd * g4.w + e4.w);
        if (grow < nrows)
            *(float4*)(out + (size_t)grow * DF + lane * 4) = o;
    }
}

// ---------------------------------------------------------------------------
// gid is sorted: boundary-flush segment sum. 128 nodes/block for parallelism.
__global__ void pool_kernel(const float* __restrict__ h, const int* __restrict__ gid,
                            float* __restrict__ pool, int N) {
    int c  = threadIdx.x;
    int n0 = blockIdx.x * 128;
    if (n0 >= N) return;
    int curg = __ldg(gid + n0);
    float acc = 0.f;
    #pragma unroll 4
    for (int i = 0; i < 128; ++i) {
        int n = n0 + i;
        if (n >= N) break;
        int g = __ldg(gid + n);
        if (g != curg) {
            atomicAdd(&pool[(size_t)curg * DF + c], acc);
            acc = 0.f;
            curg = g;
        }
        acc += __ldg(h + (size_t)n * DF + c);
    }
    atomicAdd(&pool[(size_t)curg * DF + c], acc);
}

// ---------------------------------------------------------------------------
__global__ void head_kernel(const float* __restrict__ pool, const float* __restrict__ desc,
                            const float* __restrict__ fc1W, const float* __restrict__ fc1b,
                            const float* __restrict__ n1g, const float* __restrict__ n1b,
                            const float* __restrict__ fc2W, const float* __restrict__ fc2b,
                            float* __restrict__ out, int X, int C) {
    int g = blockIdx.x;
    int t = threadIdx.x;
    int warp = t >> 5, lane = t & 31;

    __shared__ float xin[DF + 64];
    __shared__ float ss[4], qq[4];

    xin[t] = pool[(size_t)g * DF + t];
    if (t < X) xin[DF + t] = desc[(size_t)g * X + t];
    __syncthreads();

    int K = DF + X;
    float acc = fc1b[t];
    for (int k = 0; k < K; ++k)
        acc = fmaf(xin[k], __ldg(fc1W + (size_t)k * DF + t), acc);

    float s = acc, q = acc * acc;
    #pragma unroll
    for (int off = 16; off > 0; off >>= 1) {
        s += __shfl_xor_sync(0xFFFFFFFFu, s, off);
        q += __shfl_xor_sync(0xFFFFFFFFu, q, off);
    }
    if (lane == 0) { ss[warp] = s; qq[warp] = q; }
    __syncthreads();
    s = ss[0] + ss[1] + ss[2] + ss[3];
    q = qq[0] + qq[1] + qq[2] + qq[3];
    float mu   = s * (1.0f / 128.0f);
    float var  = q * (1.0f / 128.0f) - mu * mu;
    float rstd = rsqrtf(var + 1e-5f);
    float y = fmaxf(0.f, (acc - mu) * rstd * n1g[t] + n1b[t]);

    for (int c = 0; c < C; ++c) {
        float p = y * __ldg(fc2W + (size_t)t * C + c);
        #pragma unroll
        for (int off = 16; off > 0; off >>= 1)
            p += __shfl_xor_sync(0xFFFFFFFFu, p, off);
        __syncthreads();
        if (lane == 0) ss[warp] = p;
        __syncthreads();
        if (t == 0) out[(size_t)g * C + c] = ss[0] + ss[1] + ss[2] + ss[3] + fc2b[c];
    }
}

// ---------------------------------------------------------------------------
extern "C" void kernel_launch(void* const* d_in, const int* in_sizes, int n_in,
                              void* d_out, int out_size) {
    const float* h    = (const float*)d_in[0];
    const float* desc = (const float*)d_in[1];
    const int*   src  = (const int*)d_in[2];
    const int*   dst  = (const int*)d_in[3];
    const int*   gid  = (const int*)d_in[4];
    const float* W1   = (const float*)d_in[5];
    const float* b1   = (const float*)d_in[6];
    const float* g1   = (const float*)d_in[7];
    const float* be1  = (const float*)d_in[8];
    const float* W2   = (const float*)d_in[9];
    const float* b2   = (const float*)d_in[10];
    const float* eps  = (const float*)d_in[11];
    const float* ng   = (const float*)d_in[12];
    const float* nb   = (const float*)d_in[13];
    const float* fc1W = (const float*)d_in[14];
    const float* fc1b = (const float*)d_in[15];
    const float* n1g  = (const float*)d_in[16];
    const float* n1b  = (const float*)d_in[17];
    const float* fc2W = (const float*)d_in[18];
    const float* fc2b = (const float*)d_in[19];
    float* out = (float*)d_out;

    int N = in_sizes[0] / DF;
    int E = in_sizes[2];
    int L = in_sizes[11];
    int X = in_sizes[14] / DF - DF;
    if (X <= 0) X = 16;
    int G = in_sizes[1] / X;
    int C = in_sizes[18] / DF;
    if (C <= 0) C = 1;
    if (N > NMAX) N = NMAX;
    if (G > GMAX) G = GMAX;

    float *bufA, *bufB, *bufC, *pool;
    cudaGetSymbolAddress((void**)&bufA, g_bufA);
    cudaGetSymbolAddress((void**)&bufB, g_bufB);
    cudaGetSymbolAddress((void**)&bufC, g_bufC);
    cudaGetSymbolAddress((void**)&pool, g_pool);

    const int SMEM_BYTES = (16384 + 8704 + 3 * DF) * sizeof(float); // 101,888
    cudaFuncSetAttribute(gemm_tf32_ln_relu,
                         cudaFuncAttributeMaxDynamicSharedMemorySize, SMEM_BYTES);

    int gb = (N + 63) / 64;
    int ewarps  = (E + 3) / 4;
    int eblocks = (ewarps * 32 + 255) / 256;

    const float* hcur = h;
    for (int l = 0; l < L; ++l) {
        cudaMemsetAsync(bufA, 0, (size_t)N * DF * sizeof(float));
        edge_kernel<<<eblocks, 256>>>(hcur, src, dst, bufA, E);
        gemm_tf32_ln_relu<<<gb, 256, SMEM_BYTES>>>(
            bufA, hcur, eps, l,
            W1 + (size_t)l * DF * DF, b1 + (size_t)l * DF,
            g1 + (size_t)l * DF, be1 + (size_t)l * DF, bufB, N);
        gemm_tf32_ln_relu<<<gb, 256, SMEM_BYTES>>>(
            bufB, nullptr, nullptr, 0,
            W2 + (size_t)l * DF * DF, b2 + (size_t)l * DF,
            ng + (size_t)l * DF, nb + (size_t)l * DF, bufC, N);
        hcur = bufC;
    }

    cudaMemsetAsync(pool, 0, (size_t)G * DF * sizeof(float));
    pool_kernel<<<(N + 127) / 128, 128>>>(hcur, gid, pool, N);
    head_kernel<<<G, 128>>>(pool, desc, fc1W, fc1b, n1g, n1b, fc2W, fc2b, out, X, C);
}

// round 4
// speedup vs baseline: 3.2764x; 1.6883x over previous
#include <cuda_runtime.h>
#include <cuda_bf16.h>
#include <cstdint>

#define DF 128
#define NMAX 100000
#define EMAX 1600000
#define GMAX 1024

// persistent scratch (no allocations allowed)
__device__ float g_bufA[(size_t)NMAX * DF];
__device__ float g_bufB[(size_t)NMAX * DF];
__device__ float g_bufC[(size_t)NMAX * DF];
__device__ float g_pool[(size_t)GMAX * DF];
__device__ int   g_deg[NMAX];
__device__ int   g_rowptr[NMAX + 1];
__device__ int   g_cursor[NMAX];
__device__ int   g_csrc[EMAX];
__device__ int   g_bsum[1024];

__device__ __forceinline__ float to_tf32(float f) {
    float o;
    asm("cvt.rna.tf32.f32 %0, %1;" : "=f"(o) : "f"(f));
    return o;
}

// ---------------------------------------------------------------------------
// CSR build: degree histogram -> exclusive scan -> scatter
__global__ void deg_kernel(const int* __restrict__ dst, int* __restrict__ deg, int E) {
    int i = blockIdx.x * blockDim.x + threadIdx.x;
    if (i < E) atomicAdd(&deg[__ldg(dst + i)], 1);
}

__global__ void scan1_kernel(const int* __restrict__ deg, int* __restrict__ rowptr,
                             int* __restrict__ bsum, int N) {
    __shared__ int sh[1024];
    int tid = threadIdx.x;
    int i = blockIdx.x * 1024 + tid;
    int v = (i < N) ? deg[i] : 0;
    sh[tid] = v;
    __syncthreads();
    #pragma unroll
    for (int off = 1; off < 1024; off <<= 1) {
        int t = (tid >= off) ? sh[tid - off] : 0;
        __syncthreads();
        sh[tid] += t;
        __syncthreads();
    }
    if (i < N) rowptr[i] = sh[tid] - v;            // exclusive within block
    if (tid == 1023) bsum[blockIdx.x] = sh[1023];  // block total
}

__global__ void scan2_kernel(int* __restrict__ bsum, int nb) {
    if (threadIdx.x == 0 && blockIdx.x == 0) {
        int acc = 0;
        for (int i = 0; i < nb; ++i) {
            int v = bsum[i];
            bsum[i] = acc;
            acc += v;
        }
    }
}

__global__ void scan3_kernel(int* __restrict__ rowptr, const int* __restrict__ bsum,
                             int N, int E) {
    int i = blockIdx.x * 1024 + threadIdx.x;
    if (i < N) rowptr[i] += bsum[blockIdx.x];
    if (i == 0) rowptr[N] = E;
}

__global__ void scatter_kernel(const int* __restrict__ src, const int* __restrict__ dst,
                               int* __restrict__ cursor, int* __restrict__ csrc, int E) {
    int i = blockIdx.x * blockDim.x + threadIdx.x;
    if (i < E) {
        int pos = atomicAdd(&cursor[__ldg(dst + i)], 1);
        csrc[pos] = __ldg(src + i);
    }
}

// ---------------------------------------------------------------------------
// Pull aggregation: one warp per dst node, register accumulation, single store.
__global__ void agg_kernel(const float* __restrict__ h, const int* __restrict__ rowptr,
                           const int* __restrict__ csrc, float* __restrict__ agg, int N) {
    int v    = (blockIdx.x * blockDim.x + threadIdx.x) >> 5;
    int lane = threadIdx.x & 31;
    if (v >= N) return;
    int beg = __ldg(rowptr + v), end = __ldg(rowptr + v + 1);
    float4 acc = make_float4(0.f, 0.f, 0.f, 0.f);
    int i = beg;
    for (; i + 4 <= end; i += 4) {
        int u0 = __ldg(csrc + i), u1 = __ldg(csrc + i + 1);
        int u2 = __ldg(csrc + i + 2), u3 = __ldg(csrc + i + 3);
        float4 a = *(const float4*)(h + (size_t)u0 * DF + lane * 4);
        float4 b = *(const float4*)(h + (size_t)u1 * DF + lane * 4);
        float4 c = *(const float4*)(h + (size_t)u2 * DF + lane * 4);
        float4 d = *(const float4*)(h + (size_t)u3 * DF + lane * 4);
        acc.x += a.x + b.x + c.x + d.x;
        acc.y += a.y + b.y + c.y + d.y;
        acc.z += a.z + b.z + c.z + d.z;
        acc.w += a.w + b.w + c.w + d.w;
    }
    for (; i < end; ++i) {
        int u = __ldg(csrc + i);
        float4 a = *(const float4*)(h + (size_t)u * DF + lane * 4);
        acc.x += a.x; acc.y += a.y; acc.z += a.z; acc.w += a.w;
    }
    *(float4*)(agg + (size_t)v * DF + lane * 4) = acc;
}

// ---------------------------------------------------------------------------
// Persistent tf32 tensor-core GEMM, fused residual + bias + LayerNorm + ReLU.
// W staged to smem ONCE per block; block loops over 64-row tiles.
__global__ void __launch_bounds__(256, 2)
gemm_tf32_ln_relu(const float* __restrict__ x, const float* __restrict__ hres,
                  const float* __restrict__ epsArr, int layer,
                  const float* __restrict__ W, const float* __restrict__ bias,
                  const float* __restrict__ gamma, const float* __restrict__ beta,
                  float* __restrict__ out, int nrows, int ntiles) {
    extern __shared__ float smem[];
    float* Ws = smem;                  // [16 s][128 n][8 kk] = 16384 floats (64KB)
    float* Xs = smem + 16384;          // [64 rows][136] (also Cs)
    float* bs = Xs + 8704;
    float* gs = bs + DF;
    float* es = gs + DF;

    int tid  = threadIdx.x;
    int lane = tid & 31, warp = tid >> 5;

    // Stage W (float4 loads): Ws[(s*128+n)*8+kk] = tf32(W[(8s+kphys)*128+n])
    #pragma unroll
    for (int idx = tid; idx < 4096; idx += 256) {
        int n4  = idx & 31;            // n = n4*4
        int skk = idx >> 5;            // 0..127
        int s   = skk >> 3, kk = skk & 7;
        int c   = kk >> 1;
        int kphys = (kk & 1) ? (c + 4) : c;
        float4 w = *(const float4*)(W + (size_t)(8 * s + kphys) * DF + n4 * 4);
        float* p = &Ws[((s * 128 + n4 * 4) << 3) + kk];
        p[0]  = to_tf32(w.x);
        p[8]  = to_tf32(w.y);
        p[16] = to_tf32(w.z);
        p[24] = to_tf32(w.w);
    }
    if (tid < DF) { bs[tid] = bias[tid]; gs[tid] = gamma[tid]; es[tid] = beta[tid]; }

    float escale = (hres != nullptr) ? (1.0f + epsArr[layer]) : 0.0f;

    int wr = (warp & 3) * 16;
    int wc = (warp >> 2) * 64;
    int fr = lane >> 2;
    int c2 = (lane & 3) * 2;

    __syncthreads();

    for (int tile = blockIdx.x; tile < ntiles; tile += gridDim.x) {
        int rowBlk = tile * 64;

        // Stage X (+ residual), float4 loads.
        // kcol = 4*c4 + j ; s = c4>>1 ; kk = (c4&1) + 2*j
        #pragma unroll
        for (int idx = tid; idx < 64 * 32; idx += 256) {
            int r = idx >> 5, c4 = idx & 31;
            int row = rowBlk + r;
            float4 v = make_float4(0.f, 0.f, 0.f, 0.f);
            if (row < nrows) {
                v = *(const float4*)(x + (size_t)row * DF + c4 * 4);
                if (hres) {
                    float4 hv = *(const float4*)(hres + (size_t)row * DF + c4 * 4);
                    v.x = fmaf(escale, hv.x, v.x);
                    v.y = fmaf(escale, hv.y, v.y);
                    v.z = fmaf(escale, hv.z, v.z);
                    v.w = fmaf(escale, hv.w, v.w);
                }
            }
            float* p = &Xs[r * 136 + (c4 >> 1) * 8 + (c4 & 1)];
            p[0] = to_tf32(v.x);
            p[2] = to_tf32(v.y);
            p[4] = to_tf32(v.z);
            p[6] = to_tf32(v.w);
        }
        __syncthreads();

        float acc[8][4];
        #pragma unroll
        for (int j = 0; j < 8; ++j) {
            acc[j][0] = 0.f; acc[j][1] = 0.f; acc[j][2] = 0.f; acc[j][3] = 0.f;
        }

        #pragma unroll
        for (int s = 0; s < 16; ++s) {
            const float* xp = &Xs[(wr + fr) * 136 + s * 8 + c2];
            float2 alo = *(const float2*)xp;
            float2 ahi = *(const float2*)(xp + 8 * 136);
            uint32_t a0 = __float_as_uint(alo.x), a2 = __float_as_uint(alo.y);
            uint32_t a1 = __float_as_uint(ahi.x), a3 = __float_as_uint(ahi.y);

            const float* wp = &Ws[((s * 128) + wc + fr) * 8 + c2];
            float2 bv[8];
            #pragma unroll
            for (int j = 0; j < 8; ++j) bv[j] = *(const float2*)(wp + j * 64);

            #pragma unroll
            for (int j = 0; j < 8; ++j) {
                uint32_t b0 = __float_as_uint(bv[j].x), b1 = __float_as_uint(bv[j].y);
                asm volatile(
                    "mma.sync.aligned.m16n8k8.row.col.f32.tf32.tf32.f32 "
                    "{%0,%1,%2,%3}, {%4,%5,%6,%7}, {%8,%9}, {%0,%1,%2,%3};"
                    : "+f"(acc[j][0]), "+f"(acc[j][1]), "+f"(acc[j][2]), "+f"(acc[j][3])
                    : "r"(a0), "r"(a1), "r"(a2), "r"(a3), "r"(b0), "r"(b1));
            }
        }

        __syncthreads();   // Xs -> Cs reuse
        float* Cs = Xs;
        #pragma unroll
        for (int j = 0; j < 8; ++j) {
            int n = wc + j * 8 + c2;
            *(float2*)&Cs[(wr + fr) * 136 + n]     = make_float2(acc[j][0], acc[j][1]);
            *(float2*)&Cs[(wr + fr + 8) * 136 + n] = make_float2(acc[j][2], acc[j][3]);
        }
        __syncthreads();

        float4 b4 = ((const float4*)bs)[lane];
        float4 g4 = ((const float4*)gs)[lane];
        float4 e4 = ((const float4*)es)[lane];
        #pragma unroll
        for (int rr = 0; rr < 8; ++rr) {
            int lrow = warp * 8 + rr;
            int grow = rowBlk + lrow;
            float4 a = *(const float4*)&Cs[lrow * 136 + lane * 4];
            float a0 = a.x + b4.x, a1 = a.y + b4.y, a2 = a.z + b4.z, a3 = a.w + b4.w;
            float s = a0 + a1 + a2 + a3;
            float q = a0 * a0 + a1 * a1 + a2 * a2 + a3 * a3;
            #pragma unroll
            for (int off = 16; off > 0; off >>= 1) {
                s += __shfl_xor_sync(0xFFFFFFFFu, s, off);
                q += __shfl_xor_sync(0xFFFFFFFFu, q, off);
            }
            float mu   = s * (1.0f / 128.0f);
            float var  = q * (1.0f / 128.0f) - mu * mu;
            float rstd = rsqrtf(var + 1e-5f);
            float4 o;
            o.x = fmaxf(0.f, (a0 - mu) * rstd * g4.x + e4.x);
            o.y = fmaxf(0.f, (a1 - mu) * rstd * g4.y + e4.y);
            o.z = fmaxf(0.f, (a2 - mu) * rstd * g4.z + e4.z);
            o.w = fmaxf(0.f, (a3 - mu) * rstd * g4.w + e4.w);
            if (grow < nrows)
                *(float4*)(out + (size_t)grow * DF + lane * 4) = o;
        }
        __syncthreads();   // before next tile overwrites Xs
    }
}

// ---------------------------------------------------------------------------
__global__ void pool_kernel(const float* __restrict__ h, const int* __restrict__ gid,
                            float* __restrict__ pool, int N) {
    int c  = threadIdx.x;
    int n0 = blockIdx.x * 128;
    if (n0 >= N) return;
    int curg = __ldg(gid + n0);
    float acc = 0.f;
    #pragma unroll 4
    for (int i = 0; i < 128; ++i) {
        int n = n0 + i;
        if (n >= N) break;
        int g = __ldg(gid + n);
        if (g != curg) {
            atomicAdd(&pool[(size_t)curg * DF + c], acc);
            acc = 0.f;
            curg = g;
        }
        acc += __ldg(h + (size_t)n * DF + c);
    }
    atomicAdd(&pool[(size_t)curg * DF + c], acc);
}

// ---------------------------------------------------------------------------
__global__ void head_kernel(const float* __restrict__ pool, const float* __restrict__ desc,
                            const float* __restrict__ fc1W, const float* __restrict__ fc1b,
                            const float* __restrict__ n1g, const float* __restrict__ n1b,
                            const float* __restrict__ fc2W, const float* __restrict__ fc2b,
                            float* __restrict__ out, int X, int C) {
    int g = blockIdx.x;
    int t = threadIdx.x;
    int warp = t >> 5, lane = t & 31;

    __shared__ float xin[DF + 64];
    __shared__ float ss[4], qq[4];

    xin[t] = pool[(size_t)g * DF + t];
    if (t < X) xin[DF + t] = desc[(size_t)g * X + t];
    __syncthreads();

    int K = DF + X;
    float acc = fc1b[t];
    for (int k = 0; k < K; ++k)
        acc = fmaf(xin[k], __ldg(fc1W + (size_t)k * DF + t), acc);

    float s = acc, q = acc * acc;
    #pragma unroll
    for (int off = 16; off > 0; off >>= 1) {
        s += __shfl_xor_sync(0xFFFFFFFFu, s, off);
        q += __shfl_xor_sync(0xFFFFFFFFu, q, off);
    }
    if (lane == 0) { ss[warp] = s; qq[warp] = q; }
    __syncthreads();
    s = ss[0] + ss[1] + ss[2] + ss[3];
    q = qq[0] + qq[1] + qq[2] + qq[3];
    float mu   = s * (1.0f / 128.0f);
    float var  = q * (1.0f / 128.0f) - mu * mu;
    float rstd = rsqrtf(var + 1e-5f);
    float y = fmaxf(0.f, (acc - mu) * rstd * n1g[t] + n1b[t]);

    for (int c = 0; c < C; ++c) {
        float p = y * __ldg(fc2W + (size_t)t * C + c);
        #pragma unroll
        for (int off = 16; off > 0; off >>= 1)
            p += __shfl_xor_sync(0xFFFFFFFFu, p, off);
        __syncthreads();
        if (lane == 0) ss[warp] = p;
        __syncthreads();
        if (t == 0) out[(size_t)g * C + c] = ss[0] + ss[1] + ss[2] + ss[3] + fc2b[c];
    }
}

// ---------------------------------------------------------------------------
extern "C" void kernel_launch(void* const* d_in, const int* in_sizes, int n_in,
                              void* d_out, int out_size) {
    const float* h    = (const float*)d_in[0];
    const float* desc = (const float*)d_in[1];
    const int*   src  = (const int*)d_in[2];
    const int*   dst  = (const int*)d_in[3];
    const int*   gid  = (const int*)d_in[4];
    const float* W1   = (const float*)d_in[5];
    const float* b1   = (const float*)d_in[6];
    const float* g1   = (const float*)d_in[7];
    const float* be1  = (const float*)d_in[8];
    const float* W2   = (const float*)d_in[9];
    const float* b2   = (const float*)d_in[10];
    const float* eps  = (const float*)d_in[11];
    const float* ng   = (const float*)d_in[12];
    const float* nb   = (const float*)d_in[13];
    const float* fc1W = (const float*)d_in[14];
    const float* fc1b = (const float*)d_in[15];
    const float* n1g  = (const float*)d_in[16];
    const float* n1b  = (const float*)d_in[17];
    const float* fc2W = (const float*)d_in[18];
    const float* fc2b = (const float*)d_in[19];
    float* out = (float*)d_out;

    int N = in_sizes[0] / DF;
    int E = in_sizes[2];
    int L = in_sizes[11];
    int X = in_sizes[14] / DF - DF;
    if (X <= 0) X = 16;
    int G = in_sizes[1] / X;
    int C = in_sizes[18] / DF;
    if (C <= 0) C = 1;
    if (N > NMAX) N = NMAX;
    if (G > GMAX) G = GMAX;
    if (E > EMAX) E = EMAX;

    float *bufA, *bufB, *bufC, *pool;
    int *degp, *rowptr, *cursor, *csrc, *bsum;
    cudaGetSymbolAddress((void**)&bufA, g_bufA);
    cudaGetSymbolAddress((void**)&bufB, g_bufB);
    cudaGetSymbolAddress((void**)&bufC, g_bufC);
    cudaGetSymbolAddress((void**)&pool, g_pool);
    cudaGetSymbolAddress((void**)&degp, g_deg);
    cudaGetSymbolAddress((void**)&rowptr, g_rowptr);
    cudaGetSymbolAddress((void**)&cursor, g_cursor);
    cudaGetSymbolAddress((void**)&csrc, g_csrc);
    cudaGetSymbolAddress((void**)&bsum, g_bsum);

    const int SMEM_BYTES = (16384 + 8704 + 3 * DF) * sizeof(float); // 101,888
    cudaFuncSetAttribute(gemm_tf32_ln_relu,
                         cudaFuncAttributeMaxDynamicSharedMemorySize, SMEM_BYTES);

    // --- CSR build (once per launch) ---
    int nb_scan = (N + 1023) / 1024;
    cudaMemsetAsync(degp, 0, (size_t)N * sizeof(int));
    deg_kernel<<<(E + 255) / 256, 256>>>(dst, degp, E);
    scan1_kernel<<<nb_scan, 1024>>>(degp, rowptr, bsum, N);
    scan2_kernel<<<1, 32>>>(bsum, nb_scan);
    scan3_kernel<<<nb_scan, 1024>>>(rowptr, bsum, N, E);
    cudaMemcpyAsync(cursor, rowptr, (size_t)N * sizeof(int), cudaMemcpyDeviceToDevice);
    scatter_kernel<<<(E + 255) / 256, 256>>>(src, dst, cursor, csrc, E);

    int ntiles = (N + 63) / 64;
    int gemm_grid = ntiles < 304 ? ntiles : 304;
    int agg_grid  = (N * 32 + 255) / 256;

    const float* hcur = h;
    for (int l = 0; l < L; ++l) {
        agg_kernel<<<agg_grid, 256>>>(hcur, rowptr, csrc, bufA, N);
        gemm_tf32_ln_relu<<<gemm_grid, 256, SMEM_BYTES>>>(
            bufA, hcur, eps, l,
            W1 + (size_t)l * DF * DF, b1 + (size_t)l * DF,
            g1 + (size_t)l * DF, be1 + (size_t)l * DF, bufB, N, ntiles);
        gemm_tf32_ln_relu<<<gemm_grid, 256, SMEM_BYTES>>>(
            bufB, nullptr, nullptr, 0,
            W2 + (size_t)l * DF * DF, b2 + (size_t)l * DF,
            ng + (size_t)l * DF, nb + (size_t)l * DF, bufC, N, ntiles);
        hcur = bufC;
    }

    cudaMemsetAsync(pool, 0, (size_t)G * DF * sizeof(float));
    pool_kernel<<<(N + 127) / 128, 128>>>(hcur, gid, pool, N);
    head_kernel<<<G, 128>>>(pool, desc, fc1W, fc1b, n1g, n1b, fc2W, fc2b, out, X, C);
}

// round 5
// speedup vs baseline: 3.3160x; 1.0121x over previous
#include <cuda_runtime.h>
#include <cuda_bf16.h>
#include <cstdint>

#define DF 128
#define NMAX 100000
#define EMAX 1600000
#define GMAX 1024

// persistent scratch (no allocations allowed)
__device__ float g_bufA[(size_t)NMAX * DF];
__device__ float g_bufC[(size_t)NMAX * DF];
__device__ float g_pool[(size_t)GMAX * DF];
__device__ int   g_deg[NMAX];
__device__ int   g_rowptr[NMAX + 1];
__device__ int   g_cursor[NMAX];
__device__ int   g_csrc[EMAX];
__device__ int   g_bsum[1024];

__device__ __forceinline__ float to_tf32(float f) {
    float o;
    asm("cvt.rna.tf32.f32 %0, %1;" : "=f"(o) : "f"(f));
    return o;
}

// ---------------------------------------------------------------------------
// CSR build: degree histogram -> exclusive scan -> scatter
__global__ void deg_kernel(const int* __restrict__ dst, int* __restrict__ deg, int E) {
    int i = blockIdx.x * blockDim.x + threadIdx.x;
    if (i < E) atomicAdd(&deg[__ldg(dst + i)], 1);
}

__global__ void scan1_kernel(const int* __restrict__ deg, int* __restrict__ rowptr,
                             int* __restrict__ bsum, int N) {
    __shared__ int sh[1024];
    int tid = threadIdx.x;
    int i = blockIdx.x * 1024 + tid;
    int v = (i < N) ? deg[i] : 0;
    sh[tid] = v;
    __syncthreads();
    #pragma unroll
    for (int off = 1; off < 1024; off <<= 1) {
        int t = (tid >= off) ? sh[tid - off] : 0;
        __syncthreads();
        sh[tid] += t;
        __syncthreads();
    }
    if (i < N) rowptr[i] = sh[tid] - v;
    if (tid == 1023) bsum[blockIdx.x] = sh[1023];
}

__global__ void scan2_kernel(int* __restrict__ bsum, int nb) {
    if (threadIdx.x == 0 && blockIdx.x == 0) {
        int acc = 0;
        for (int i = 0; i < nb; ++i) {
            int v = bsum[i];
            bsum[i] = acc;
            acc += v;
        }
    }
}

__global__ void scan3_kernel(int* __restrict__ rowptr, const int* __restrict__ bsum,
                             int N, int E) {
    int i = blockIdx.x * 1024 + threadIdx.x;
    if (i < N) rowptr[i] += bsum[blockIdx.x];
    if (i == 0) rowptr[N] = E;
}

__global__ void scatter_kernel(const int* __restrict__ src, const int* __restrict__ dst,
                               int* __restrict__ cursor, int* __restrict__ csrc, int E) {
    int i = blockIdx.x * blockDim.x + threadIdx.x;
    if (i < E) {
        int pos = atomicAdd(&cursor[__ldg(dst + i)], 1);
        csrc[pos] = __ldg(src + i);
    }
}

// ---------------------------------------------------------------------------
// Pull aggregation: one warp per dst node, register accumulation, single store.
__global__ void agg_kernel(const float* __restrict__ h, const int* __restrict__ rowptr,
                           const int* __restrict__ csrc, float* __restrict__ agg, int N) {
    int v    = (blockIdx.x * blockDim.x + threadIdx.x) >> 5;
    int lane = threadIdx.x & 31;
    if (v >= N) return;
    int beg = __ldg(rowptr + v), end = __ldg(rowptr + v + 1);
    float4 acc = make_float4(0.f, 0.f, 0.f, 0.f);
    int i = beg;
    for (; i + 4 <= end; i += 4) {
        int u0 = __ldg(csrc + i), u1 = __ldg(csrc + i + 1);
        int u2 = __ldg(csrc + i + 2), u3 = __ldg(csrc + i + 3);
        float4 a = *(const float4*)(h + (size_t)u0 * DF + lane * 4);
        float4 b = *(const float4*)(h + (size_t)u1 * DF + lane * 4);
        float4 c = *(const float4*)(h + (size_t)u2 * DF + lane * 4);
        float4 d = *(const float4*)(h + (size_t)u3 * DF + lane * 4);
        acc.x += a.x + b.x + c.x + d.x;
        acc.y += a.y + b.y + c.y + d.y;
        acc.z += a.z + b.z + c.z + d.z;
        acc.w += a.w + b.w + c.w + d.w;
    }
    for (; i < end; ++i) {
        int u = __ldg(csrc + i);
        float4 a = *(const float4*)(h + (size_t)u * DF + lane * 4);
        acc.x += a.x; acc.y += a.y; acc.z += a.z; acc.w += a.w;
    }
    *(float4*)(agg + (size_t)v * DF + lane * 4) = acc;
}

// ---------------------------------------------------------------------------
// Fully fused GIN layer MLP: persistent kernel, both W1 and W2 staged to smem
// once per block. Per 128-row tile:
//   stage X(+residual) -> mma(W1) -> LN1+ReLU (in-place re-permute to tf32
//   A-layout in smem) -> mma(W2) -> LN2+ReLU -> single gmem store.
// CTA tile 128x128, 8 warps, warp tile 32x64 (two 16-row sub-blocks sharing
// the B fragments -> half the LDS traffic for W).
__global__ void __launch_bounds__(256, 1)
layer_fused(const float* __restrict__ x, const float* __restrict__ hres,
            const float* __restrict__ epsArr, int layer,
            const float* __restrict__ W1, const float* __restrict__ b1,
            const float* __restrict__ g1, const float* __restrict__ be1,
            const float* __restrict__ W2, const float* __restrict__ b2,
            const float* __restrict__ ng, const float* __restrict__ nb,
            float* __restrict__ out, int nrows, int ntiles) {
    extern __shared__ float smem[];
    float* Ws1 = smem;                   // 16384 floats
    float* Ws2 = smem + 16384;           // 16384 floats
    float* Xs  = smem + 32768;           // [128 rows][136] = 17408 floats
    float* prm = smem + 32768 + 17408;   // 6 x 128
    float* bs1 = prm, *gs1 = prm + 128, *es1 = prm + 256;
    float* bs2 = prm + 384, *gs2 = prm + 512, *es2 = prm + 640;

    int tid  = threadIdx.x;
    int lane = tid & 31, warp = tid >> 5;

    // Stage W1 and W2 (float4 loads, tf32, k-interleaved):
    // Ws[(s*128+n)*8+kk] = tf32(W[(8s+kphys)*128+n]), kphys=(kk&1)?(kk>>1)+4:(kk>>1)
    #pragma unroll
    for (int idx = tid; idx < 4096; idx += 256) {
        int n4  = idx & 31;
        int skk = idx >> 5;
        int s   = skk >> 3, kk = skk & 7;
        int c   = kk >> 1;
        int kphys = (kk & 1) ? (c + 4) : c;
        size_t go = (size_t)(8 * s + kphys) * DF + n4 * 4;
        float4 wa = *(const float4*)(W1 + go);
        float4 wb = *(const float4*)(W2 + go);
        float* pa = &Ws1[((s * 128 + n4 * 4) << 3) + kk];
        float* pb = &Ws2[((s * 128 + n4 * 4) << 3) + kk];
        pa[0] = to_tf32(wa.x); pa[8] = to_tf32(wa.y); pa[16] = to_tf32(wa.z); pa[24] = to_tf32(wa.w);
        pb[0] = to_tf32(wb.x); pb[8] = to_tf32(wb.y); pb[16] = to_tf32(wb.z); pb[24] = to_tf32(wb.w);
    }
    if (tid < DF) {
        bs1[tid] = b1[tid]; gs1[tid] = g1[tid]; es1[tid] = be1[tid];
        bs2[tid] = b2[tid]; gs2[tid] = ng[tid]; es2[tid] = nb[tid];
    }

    float escale = 1.0f + epsArr[layer];

    int wr = (warp & 3) * 32;      // warp row base (two 16-row sub-blocks)
    int wc = (warp >> 2) * 64;     // warp col base
    int fr = lane >> 2;
    int c2 = (lane & 3) * 2;

    __syncthreads();

    for (int tile = blockIdx.x; tile < ntiles; tile += gridDim.x) {
        int rowBlk = tile * 128;

        // ---- stage X + residual (tf32, interleaved) ----
        #pragma unroll
        for (int idx = tid; idx < 128 * 32; idx += 256) {
            int r = idx >> 5, c4 = idx & 31;
            int row = rowBlk + r;
            float4 v = make_float4(0.f, 0.f, 0.f, 0.f);
            if (row < nrows) {
                v = *(const float4*)(x + (size_t)row * DF + c4 * 4);
                float4 hv = *(const float4*)(hres + (size_t)row * DF + c4 * 4);
                v.x = fmaf(escale, hv.x, v.x);
                v.y = fmaf(escale, hv.y, v.y);
                v.z = fmaf(escale, hv.z, v.z);
                v.w = fmaf(escale, hv.w, v.w);
            }
            float* p = &Xs[r * 136 + (c4 >> 1) * 8 + (c4 & 1)];
            p[0] = to_tf32(v.x);
            p[2] = to_tf32(v.y);
            p[4] = to_tf32(v.z);
            p[6] = to_tf32(v.w);
        }
        __syncthreads();

        float acc[2][8][4];

        // ================= pass 1: X @ W1 =================
        #pragma unroll
        for (int rb = 0; rb < 2; ++rb)
            #pragma unroll
            for (int j = 0; j < 8; ++j) {
                acc[rb][j][0] = 0.f; acc[rb][j][1] = 0.f;
                acc[rb][j][2] = 0.f; acc[rb][j][3] = 0.f;
            }
        #pragma unroll
        for (int s = 0; s < 16; ++s) {
            uint32_t a[2][4];
            #pragma unroll
            for (int rb = 0; rb < 2; ++rb) {
                const float* xp = &Xs[(wr + rb * 16 + fr) * 136 + s * 8 + c2];
                float2 alo = *(const float2*)xp;
                float2 ahi = *(const float2*)(xp + 8 * 136);
                a[rb][0] = __float_as_uint(alo.x); a[rb][2] = __float_as_uint(alo.y);
                a[rb][1] = __float_as_uint(ahi.x); a[rb][3] = __float_as_uint(ahi.y);
            }
            const float* wp = &Ws1[((s * 128) + wc + fr) * 8 + c2];
            #pragma unroll
            for (int j = 0; j < 8; ++j) {
                float2 bvj = *(const float2*)(wp + j * 64);
                uint32_t b0 = __float_as_uint(bvj.x), bq = __float_as_uint(bvj.y);
                #pragma unroll
                for (int rb = 0; rb < 2; ++rb)
                    asm volatile(
                        "mma.sync.aligned.m16n8k8.row.col.f32.tf32.tf32.f32 "
                        "{%0,%1,%2,%3}, {%4,%5,%6,%7}, {%8,%9}, {%0,%1,%2,%3};"
                        : "+f"(acc[rb][j][0]), "+f"(acc[rb][j][1]),
                          "+f"(acc[rb][j][2]), "+f"(acc[rb][j][3])
                        : "r"(a[rb][0]), "r"(a[rb][1]), "r"(a[rb][2]), "r"(a[rb][3]),
                          "r"(b0), "r"(bq));
            }
        }
        __syncthreads();
        #pragma unroll
        for (int rb = 0; rb < 2; ++rb)
            #pragma unroll
            for (int j = 0; j < 8; ++j) {
                int n = wc + j * 8 + c2;
                *(float2*)&Xs[(wr + rb * 16 + fr) * 136 + n]     = make_float2(acc[rb][j][0], acc[rb][j][1]);
                *(float2*)&Xs[(wr + rb * 16 + fr + 8) * 136 + n] = make_float2(acc[rb][j][2], acc[rb][j][3]);
            }
        __syncthreads();

        // ---- LN1 + ReLU, in-place re-permute to tf32 A-layout ----
        {
            float4 b4 = ((const float4*)bs1)[lane];
            float4 g4 = ((const float4*)gs1)[lane];
            float4 e4 = ((const float4*)es1)[lane];
            #pragma unroll
            for (int rr = 0; rr < 16; ++rr) {
                int lrow = warp * 16 + rr;
                float* R = &Xs[lrow * 136];
                float4 aa = *(const float4*)&R[lane * 4];
                float a0 = aa.x + b4.x, a1 = aa.y + b4.y, a2 = aa.z + b4.z, a3 = aa.w + b4.w;
                float s = a0 + a1 + a2 + a3;
                float q = a0 * a0 + a1 * a1 + a2 * a2 + a3 * a3;
                #pragma unroll
                for (int off = 16; off > 0; off >>= 1) {
                    s += __shfl_xor_sync(0xFFFFFFFFu, s, off);
                    q += __shfl_xor_sync(0xFFFFFFFFu, q, off);
                }
                float mu   = s * (1.0f / 128.0f);
                float var  = q * (1.0f / 128.0f) - mu * mu;
                float rstd = rsqrtf(var + 1e-5f);
                float o0 = fmaxf(0.f, (a0 - mu) * rstd * g4.x + e4.x);
                float o1 = fmaxf(0.f, (a1 - mu) * rstd * g4.y + e4.y);
                float o2 = fmaxf(0.f, (a2 - mu) * rstd * g4.z + e4.z);
                float o3 = fmaxf(0.f, (a3 - mu) * rstd * g4.w + e4.w);
                // permuted positions for kcol = lane*4 + {0,1,2,3}
                int kc = lane * 4;
                int grp = (kc >> 3) * 8;
                int c0 = kc & 7;   // 0 or 4
                int p0 = grp + ((c0 < 4) ? 2 * c0 : 2 * (c0 - 4) + 1);
                // within a half-group, consecutive kcol -> positions step by 2
                R[p0]     = to_tf32(o0);
                R[p0 + 2] = to_tf32(o1);
                R[p0 + 4] = to_tf32(o2);
                R[p0 + 6] = to_tf32(o3);
            }
        }
        __syncthreads();

        // ================= pass 2: Y @ W2 =================
        #pragma unroll
        for (int rb = 0; rb < 2; ++rb)
            #pragma unroll
            for (int j = 0; j < 8; ++j) {
                acc[rb][j][0] = 0.f; acc[rb][j][1] = 0.f;
                acc[rb][j][2] = 0.f; acc[rb][j][3] = 0.f;
            }
        #pragma unroll
        for (int s = 0; s < 16; ++s) {
            uint32_t a[2][4];
            #pragma unroll
            for (int rb = 0; rb < 2; ++rb) {
                const float* xp = &Xs[(wr + rb * 16 + fr) * 136 + s * 8 + c2];
                float2 alo = *(const float2*)xp;
                float2 ahi = *(const float2*)(xp + 8 * 136);
                a[rb][0] = __float_as_uint(alo.x); a[rb][2] = __float_as_uint(alo.y);
                a[rb][1] = __float_as_uint(ahi.x); a[rb][3] = __float_as_uint(ahi.y);
            }
            const float* wp = &Ws2[((s * 128) + wc + fr) * 8 + c2];
            #pragma unroll
            for (int j = 0; j < 8; ++j) {
                float2 bvj = *(const float2*)(wp + j * 64);
                uint32_t b0 = __float_as_uint(bvj.x), bq = __float_as_uint(bvj.y);
                #pragma unroll
                for (int rb = 0; rb < 2; ++rb)
                    asm volatile(
                        "mma.sync.aligned.m16n8k8.row.col.f32.tf32.tf32.f32 "
                        "{%0,%1,%2,%3}, {%4,%5,%6,%7}, {%8,%9}, {%0,%1,%2,%3};"
                        : "+f"(acc[rb][j][0]), "+f"(acc[rb][j][1]),
                          "+f"(acc[rb][j][2]), "+f"(acc[rb][j][3])
                        : "r"(a[rb][0]), "r"(a[rb][1]), "r"(a[rb][2]), "r"(a[rb][3]),
                          "r"(b0), "r"(bq));
            }
        }
        __syncthreads();
        #pragma unroll
        for (int rb = 0; rb < 2; ++rb)
            #pragma unroll
            for (int j = 0; j < 8; ++j) {
                int n = wc + j * 8 + c2;
                *(float2*)&Xs[(wr + rb * 16 + fr) * 136 + n]     = make_float2(acc[rb][j][0], acc[rb][j][1]);
                *(float2*)&Xs[(wr + rb * 16 + fr + 8) * 136 + n] = make_float2(acc[rb][j][2], acc[rb][j][3]);
            }
        __syncthreads();

        // ---- LN2 + ReLU -> gmem ----
        {
            float4 b4 = ((const float4*)bs2)[lane];
            float4 g4 = ((const float4*)gs2)[lane];
            float4 e4 = ((const float4*)es2)[lane];
            #pragma unroll
            for (int rr = 0; rr < 16; ++rr) {
                int lrow = warp * 16 + rr;
                int grow = rowBlk + lrow;
                float4 aa = *(const float4*)&Xs[lrow * 136 + lane * 4];
                float a0 = aa.x + b4.x, a1 = aa.y + b4.y, a2 = aa.z + b4.z, a3 = aa.w + b4.w;
                float s = a0 + a1 + a2 + a3;
                float q = a0 * a0 + a1 * a1 + a2 * a2 + a3 * a3;
                #pragma unroll
                for (int off = 16; off > 0; off >>= 1) {
                    s += __shfl_xor_sync(0xFFFFFFFFu, s, off);
                    q += __shfl_xor_sync(0xFFFFFFFFu, q, off);
                }
                float mu   = s * (1.0f / 128.0f);
                float var  = q * (1.0f / 128.0f) - mu * mu;
                float rstd = rsqrtf(var + 1e-5f);
                float4 o;
                o.x = fmaxf(0.f, (a0 - mu) * rstd * g4.x + e4.x);
                o.y = fmaxf(0.f, (a1 - mu) * rstd * g4.y + e4.y);
                o.z = fmaxf(0.f, (a2 - mu) * rstd * g4.z + e4.z);
                o.w = fmaxf(0.f, (a3 - mu) * rstd * g4.w + e4.w);
                if (grow < nrows)
                    *(float4*)(out + (size_t)grow * DF + lane * 4) = o;
            }
        }
        __syncthreads();
    }
}

// ---------------------------------------------------------------------------
__global__ void pool_kernel(const float* __restrict__ h, const int* __restrict__ gid,
                            float* __restrict__ pool, int N) {
    int c  = threadIdx.x;
    int n0 = blockIdx.x * 128;
    if (n0 >= N) return;
    int curg = __ldg(gid + n0);
    float acc = 0.f;
    #pragma unroll 4
    for (int i = 0; i < 128; ++i) {
        int n = n0 + i;
        if (n >= N) break;
        int g = __ldg(gid + n);
        if (g != curg) {
            atomicAdd(&pool[(size_t)curg * DF + c], acc);
            acc = 0.f;
            curg = g;
        }
        acc += __ldg(h + (size_t)n * DF + c);
    }
    atomicAdd(&pool[(size_t)curg * DF + c], acc);
}

// ---------------------------------------------------------------------------
__global__ void head_kernel(const float* __restrict__ pool, const float* __restrict__ desc,
                            const float* __restrict__ fc1W, const float* __restrict__ fc1b,
                            const float* __restrict__ n1g, const float* __restrict__ n1b,
                            const float* __restrict__ fc2W, const float* __restrict__ fc2b,
                            float* __restrict__ out, int X, int C) {
    int g = blockIdx.x;
    int t = threadIdx.x;
    int warp = t >> 5, lane = t & 31;

    __shared__ float xin[DF + 64];
    __shared__ float ss[4], qq[4];

    xin[t] = pool[(size_t)g * DF + t];
    if (t < X) xin[DF + t] = desc[(size_t)g * X + t];
    __syncthreads();

    int K = DF + X;
    float acc = fc1b[t];
    for (int k = 0; k < K; ++k)
        acc = fmaf(xin[k], __ldg(fc1W + (size_t)k * DF + t), acc);

    float s = acc, q = acc * acc;
    #pragma unroll
    for (int off = 16; off > 0; off >>= 1) {
        s += __shfl_xor_sync(0xFFFFFFFFu, s, off);
        q += __shfl_xor_sync(0xFFFFFFFFu, q, off);
    }
    if (lane == 0) { ss[warp] = s; qq[warp] = q; }
    __syncthreads();
    s = ss[0] + ss[1] + ss[2] + ss[3];
    q = qq[0] + qq[1] + qq[2] + qq[3];
    float mu   = s * (1.0f / 128.0f);
    float var  = q * (1.0f / 128.0f) - mu * mu;
    float rstd = rsqrtf(var + 1e-5f);
    float y = fmaxf(0.f, (acc - mu) * rstd * n1g[t] + n1b[t]);

    for (int c = 0; c < C; ++c) {
        float p = y * __ldg(fc2W + (size_t)t * C + c);
        #pragma unroll
        for (int off = 16; off > 0; off >>= 1)
            p += __shfl_xor_sync(0xFFFFFFFFu, p, off);
        __syncthreads();
        if (lane == 0) ss[warp] = p;
        __syncthreads();
        if (t == 0) out[(size_t)g * C + c] = ss[0] + ss[1] + ss[2] + ss[3] + fc2b[c];
    }
}

// ---------------------------------------------------------------------------
extern "C" void kernel_launch(void* const* d_in, const int* in_sizes, int n_in,
                              void* d_out, int out_size) {
    const float* h    = (const float*)d_in[0];
    const float* desc = (const float*)d_in[1];
    const int*   src  = (const int*)d_in[2];
    const int*   dst  = (const int*)d_in[3];
    const int*   gid  = (const int*)d_in[4];
    const float* W1   = (const float*)d_in[5];
    const float* b1   = (const float*)d_in[6];
    const float* g1   = (const float*)d_in[7];
    const float* be1  = (const float*)d_in[8];
    const float* W2   = (const float*)d_in[9];
    const float* b2   = (const float*)d_in[10];
    const float* eps  = (const float*)d_in[11];
    const float* ng   = (const float*)d_in[12];
    const float* nb   = (const float*)d_in[13];
    const float* fc1W = (const float*)d_in[14];
    const float* fc1b = (const float*)d_in[15];
    const float* n1g  = (const float*)d_in[16];
    const float* n1b  = (const float*)d_in[17];
    const float* fc2W = (const float*)d_in[18];
    const float* fc2b = (const float*)d_in[19];
    float* out = (float*)d_out;

    int N = in_sizes[0] / DF;
    int E = in_sizes[2];
    int L = in_sizes[11];
    int X = in_sizes[14] / DF - DF;
    if (X <= 0) X = 16;
    int G = in_sizes[1] / X;
    int C = in_sizes[18] / DF;
    if (C <= 0) C = 1;
    if (N > NMAX) N = NMAX;
    if (G > GMAX) G = GMAX;
    if (E > EMAX) E = EMAX;

    float *bufA, *bufC, *pool;
    int *degp, *rowptr, *cursor, *csrc, *bsum;
    cudaGetSymbolAddress((void**)&bufA, g_bufA);
    cudaGetSymbolAddress((void**)&bufC, g_bufC);
    cudaGetSymbolAddress((void**)&pool, g_pool);
    cudaGetSymbolAddress((void**)&degp, g_deg);
    cudaGetSymbolAddress((void**)&rowptr, g_rowptr);
    cudaGetSymbolAddress((void**)&cursor, g_cursor);
    cudaGetSymbolAddress((void**)&csrc, g_csrc);
    cudaGetSymbolAddress((void**)&bsum, g_bsum);

    const int SMEM_BYTES = (2 * 16384 + 17408 + 6 * DF) * sizeof(float); // 203,776
    cudaFuncSetAttribute(layer_fused,
                         cudaFuncAttributeMaxDynamicSharedMemorySize, SMEM_BYTES);

    // --- CSR build (once per launch) ---
    int nb_scan = (N + 1023) / 1024;
    cudaMemsetAsync(degp, 0, (size_t)N * sizeof(int));
    deg_kernel<<<(E + 255) / 256, 256>>>(dst, degp, E);
    scan1_kernel<<<nb_scan, 1024>>>(degp, rowptr, bsum, N);
    scan2_kernel<<<1, 32>>>(bsum, nb_scan);
    scan3_kernel<<<nb_scan, 1024>>>(rowptr, bsum, N, E);
    cudaMemcpyAsync(cursor, rowptr, (size_t)N * sizeof(int), cudaMemcpyDeviceToDevice);
    scatter_kernel<<<(E + 255) / 256, 256>>>(src, dst, cursor, csrc, E);

    int ntiles = (N + 127) / 128;
    int fgrid = ntiles < 148 ? ntiles : 148;
    int agg_grid = (N * 32 + 255) / 256;

    const float* hcur = h;
    for (int l = 0; l < L; ++l) {
        agg_kernel<<<agg_grid, 256>>>(hcur, rowptr, csrc, bufA, N);
        layer_fused<<<fgrid, 256, SMEM_BYTES>>>(
            bufA, hcur, eps, l,
            W1 + (size_t)l * DF * DF, b1 + (size_t)l * DF,
            g1 + (size_t)l * DF, be1 + (size_t)l * DF,
            W2 + (size_t)l * DF * DF, b2 + (size_t)l * DF,
            ng + (size_t)l * DF, nb + (size_t)l * DF,
            bufC, N, ntiles);
        hcur = bufC;
    }

    cudaMemsetAsync(pool, 0, (size_t)G * DF * sizeof(float));
    pool_kernel<<<(N + 127) / 128, 128>>>(hcur, gid, pool, N);
    head_kernel<<<G, 128>>>(pool, desc, fc1W, fc1b, n1g, n1b, fc2W, fc2b, out, X, C);
}

// round 6
// speedup vs baseline: 3.4669x; 1.0455x over previous
#include <cuda_runtime.h>
#include <cuda_bf16.h>
#include <cstdint>

#define DF 128
#define NMAX 100000
#define EMAX 1600000
#define GMAX 1024

// persistent scratch (no allocations allowed)
__device__ float g_bufA[(size_t)NMAX * DF];
__device__ float g_bufC[(size_t)NMAX * DF];
__device__ float g_pool[(size_t)GMAX * DF];
__device__ int   g_deg[NMAX];
__device__ int   g_rowptr[NMAX + 1];
__device__ int   g_cursor[NMAX];
__device__ int   g_csrc[EMAX];
__device__ int   g_bsum[1024];

__device__ __forceinline__ float to_tf32(float f) {
    float o;
    asm("cvt.rna.tf32.f32 %0, %1;" : "=f"(o) : "f"(f));
    return o;
}

// ---------------------------------------------------------------------------
// CSR build: degree histogram -> exclusive scan -> scatter
__global__ void deg_kernel(const int* __restrict__ dst, int* __restrict__ deg, int E) {
    int i = blockIdx.x * blockDim.x + threadIdx.x;
    if (i < E) atomicAdd(&deg[__ldg(dst + i)], 1);
}

__global__ void scan1_kernel(const int* __restrict__ deg, int* __restrict__ rowptr,
                             int* __restrict__ bsum, int N) {
    __shared__ int sh[1024];
    int tid = threadIdx.x;
    int i = blockIdx.x * 1024 + tid;
    int v = (i < N) ? deg[i] : 0;
    sh[tid] = v;
    __syncthreads();
    #pragma unroll
    for (int off = 1; off < 1024; off <<= 1) {
        int t = (tid >= off) ? sh[tid - off] : 0;
        __syncthreads();
        sh[tid] += t;
        __syncthreads();
    }
    if (i < N) rowptr[i] = sh[tid] - v;
    if (tid == 1023) bsum[blockIdx.x] = sh[1023];
}

__global__ void scan2_kernel(int* __restrict__ bsum, int nb) {
    if (threadIdx.x == 0 && blockIdx.x == 0) {
        int acc = 0;
        for (int i = 0; i < nb; ++i) {
            int v = bsum[i];
            bsum[i] = acc;
            acc += v;
        }
    }
}

__global__ void scan3_kernel(int* __restrict__ rowptr, const int* __restrict__ bsum,
                             int N, int E) {
    int i = blockIdx.x * 1024 + threadIdx.x;
    if (i < N) rowptr[i] += bsum[blockIdx.x];
    if (i == 0) rowptr[N] = E;
}

__global__ void scatter_kernel(const int* __restrict__ src, const int* __restrict__ dst,
                               int* __restrict__ cursor, int* __restrict__ csrc, int E) {
    int i = blockIdx.x * blockDim.x + threadIdx.x;
    if (i < E) {
        int pos = atomicAdd(&cursor[__ldg(dst + i)], 1);
        csrc[pos] = __ldg(src + i);
    }
}

// ---------------------------------------------------------------------------
// Pull aggregation: one warp per dst node, register accumulation, single store.
__global__ void agg_kernel(const float* __restrict__ h, const int* __restrict__ rowptr,
                           const int* __restrict__ csrc, float* __restrict__ agg, int N) {
    int v    = (blockIdx.x * blockDim.x + threadIdx.x) >> 5;
    int lane = threadIdx.x & 31;
    if (v >= N) return;
    int beg = __ldg(rowptr + v), end = __ldg(rowptr + v + 1);
    float4 acc = make_float4(0.f, 0.f, 0.f, 0.f);
    int i = beg;
    for (; i + 4 <= end; i += 4) {
        int u0 = __ldg(csrc + i), u1 = __ldg(csrc + i + 1);
        int u2 = __ldg(csrc + i + 2), u3 = __ldg(csrc + i + 3);
        float4 a = *(const float4*)(h + (size_t)u0 * DF + lane * 4);
        float4 b = *(const float4*)(h + (size_t)u1 * DF + lane * 4);
        float4 c = *(const float4*)(h + (size_t)u2 * DF + lane * 4);
        float4 d = *(const float4*)(h + (size_t)u3 * DF + lane * 4);
        acc.x += a.x + b.x + c.x + d.x;
        acc.y += a.y + b.y + c.y + d.y;
        acc.z += a.z + b.z + c.z + d.z;
        acc.w += a.w + b.w + c.w + d.w;
    }
    for (; i < end; ++i) {
        int u = __ldg(csrc + i);
        float4 a = *(const float4*)(h + (size_t)u * DF + lane * 4);
        acc.x += a.x; acc.y += a.y; acc.z += a.z; acc.w += a.w;
    }
    *(float4*)(agg + (size_t)v * DF + lane * 4) = acc;
}

// ---------------------------------------------------------------------------
// Fully fused GIN layer MLP: persistent kernel, both W1 and W2 in smem.
// 512 threads (16 warps) per CTA for latency hiding; warp tile 16x64.
// Per 128-row tile: stage X(+res) -> mma(W1) -> LN1+ReLU (in-place re-permute
// to tf32 A-layout) -> mma(W2) -> LN2+ReLU -> store.
__global__ void __launch_bounds__(512, 1)
layer_fused(const float* __restrict__ x, const float* __restrict__ hres,
            const float* __restrict__ epsArr, int layer,
            const float* __restrict__ W1, const float* __restrict__ b1,
            const float* __restrict__ g1, const float* __restrict__ be1,
            const float* __restrict__ W2, const float* __restrict__ b2,
            const float* __restrict__ ng, const float* __restrict__ nb,
            float* __restrict__ out, int nrows, int ntiles) {
    extern __shared__ float smem[];
    float* Ws1 = smem;                   // 16384 floats
    float* Ws2 = smem + 16384;           // 16384 floats
    float* Xs  = smem + 32768;           // [128 rows][136] = 17408 floats
    float* prm = smem + 32768 + 17408;   // 6 x 128
    float* bs1 = prm, *gs1 = prm + 128, *es1 = prm + 256;
    float* bs2 = prm + 384, *gs2 = prm + 512, *es2 = prm + 640;

    int tid  = threadIdx.x;
    int lane = tid & 31, warp = tid >> 5;

    // Stage W1 and W2 (float4 loads, tf32, k-interleaved):
    // Ws[(s*128+n)*8+kk] = tf32(W[(8s+kphys)*128+n]), kphys=(kk&1)?(kk>>1)+4:(kk>>1)
    #pragma unroll
    for (int idx = tid; idx < 4096; idx += 512) {
        int n4  = idx & 31;
        int skk = idx >> 5;
        int s   = skk >> 3, kk = skk & 7;
        int c   = kk >> 1;
        int kphys = (kk & 1) ? (c + 4) : c;
        size_t go = (size_t)(8 * s + kphys) * DF + n4 * 4;
        float4 wa = *(const float4*)(W1 + go);
        float4 wb = *(const float4*)(W2 + go);
        float* pa = &Ws1[((s * 128 + n4 * 4) << 3) + kk];
        float* pb = &Ws2[((s * 128 + n4 * 4) << 3) + kk];
        pa[0] = to_tf32(wa.x); pa[8] = to_tf32(wa.y); pa[16] = to_tf32(wa.z); pa[24] = to_tf32(wa.w);
        pb[0] = to_tf32(wb.x); pb[8] = to_tf32(wb.y); pb[16] = to_tf32(wb.z); pb[24] = to_tf32(wb.w);
    }
    if (tid < DF) {
        bs1[tid] = b1[tid]; gs1[tid] = g1[tid]; es1[tid] = be1[tid];
        bs2[tid] = b2[tid]; gs2[tid] = ng[tid]; es2[tid] = nb[tid];
    }

    float escale = 1.0f + epsArr[layer];

    int wr = (warp & 7) * 16;      // warp row base
    int wc = (warp >> 3) * 64;     // warp col base
    int fr = lane >> 2;
    int c2 = (lane & 3) * 2;

    __syncthreads();

    for (int tile = blockIdx.x; tile < ntiles; tile += gridDim.x) {
        int rowBlk = tile * 128;

        // ---- stage X + residual (tf32, interleaved) ----
        #pragma unroll
        for (int idx = tid; idx < 128 * 32; idx += 512) {
            int r = idx >> 5, c4 = idx & 31;
            int row = rowBlk + r;
            float4 v = make_float4(0.f, 0.f, 0.f, 0.f);
            if (row < nrows) {
                v = *(const float4*)(x + (size_t)row * DF + c4 * 4);
                float4 hv = *(const float4*)(hres + (size_t)row * DF + c4 * 4);
                v.x = fmaf(escale, hv.x, v.x);
                v.y = fmaf(escale, hv.y, v.y);
                v.z = fmaf(escale, hv.z, v.z);
                v.w = fmaf(escale, hv.w, v.w);
            }
            float* p = &Xs[r * 136 + (c4 >> 1) * 8 + (c4 & 1)];
            p[0] = to_tf32(v.x);
            p[2] = to_tf32(v.y);
            p[4] = to_tf32(v.z);
            p[6] = to_tf32(v.w);
        }
        __syncthreads();

        float acc[8][4];

        // ================= pass 1: X @ W1 =================
        #pragma unroll
        for (int j = 0; j < 8; ++j) {
            acc[j][0] = 0.f; acc[j][1] = 0.f; acc[j][2] = 0.f; acc[j][3] = 0.f;
        }
        #pragma unroll
        for (int s = 0; s < 16; ++s) {
            const float* xp = &Xs[(wr + fr) * 136 + s * 8 + c2];
            float2 alo = *(const float2*)xp;
            float2 ahi = *(const float2*)(xp + 8 * 136);
            uint32_t a0 = __float_as_uint(alo.x), a2 = __float_as_uint(alo.y);
            uint32_t a1 = __float_as_uint(ahi.x), a3 = __float_as_uint(ahi.y);
            const float* wp = &Ws1[((s * 128) + wc + fr) * 8 + c2];
            #pragma unroll
            for (int j = 0; j < 8; ++j) {
                float2 bvj = *(const float2*)(wp + j * 64);
                uint32_t b0 = __float_as_uint(bvj.x), bq = __float_as_uint(bvj.y);
                asm volatile(
                    "mma.sync.aligned.m16n8k8.row.col.f32.tf32.tf32.f32 "
                    "{%0,%1,%2,%3}, {%4,%5,%6,%7}, {%8,%9}, {%0,%1,%2,%3};"
                    : "+f"(acc[j][0]), "+f"(acc[j][1]), "+f"(acc[j][2]), "+f"(acc[j][3])
                    : "r"(a0), "r"(a1), "r"(a2), "r"(a3), "r"(b0), "r"(bq));
            }
        }
        __syncthreads();
        #pragma unroll
        for (int j = 0; j < 8; ++j) {
            int n = wc + j * 8 + c2;
            *(float2*)&Xs[(wr + fr) * 136 + n]     = make_float2(acc[j][0], acc[j][1]);
            *(float2*)&Xs[(wr + fr + 8) * 136 + n] = make_float2(acc[j][2], acc[j][3]);
        }
        __syncthreads();

        // ---- LN1 + ReLU, in-place re-permute to tf32 A-layout ----
        {
            float4 b4 = ((const float4*)bs1)[lane];
            float4 g4 = ((const float4*)gs1)[lane];
            float4 e4 = ((const float4*)es1)[lane];
            #pragma unroll
            for (int rr = 0; rr < 8; ++rr) {
                int lrow = warp * 8 + rr;
                float* R = &Xs[lrow * 136];
                float4 aa = *(const float4*)&R[lane * 4];
                float a0 = aa.x + b4.x, a1 = aa.y + b4.y, a2 = aa.z + b4.z, a3 = aa.w + b4.w;
                float s = a0 + a1 + a2 + a3;
                float q = a0 * a0 + a1 * a1 + a2 * a2 + a3 * a3;
                #pragma unroll
                for (int off = 16; off > 0; off >>= 1) {
                    s += __shfl_xor_sync(0xFFFFFFFFu, s, off);
                    q += __shfl_xor_sync(0xFFFFFFFFu, q, off);
                }
                float mu   = s * (1.0f / 128.0f);
                float var  = q * (1.0f / 128.0f) - mu * mu;
                float rstd = rsqrtf(var + 1e-5f);
                float o0 = fmaxf(0.f, (a0 - mu) * rstd * g4.x + e4.x);
                float o1 = fmaxf(0.f, (a1 - mu) * rstd * g4.y + e4.y);
                float o2 = fmaxf(0.f, (a2 - mu) * rstd * g4.z + e4.z);
                float o3 = fmaxf(0.f, (a3 - mu) * rstd * g4.w + e4.w);
                int kc = lane * 4;
                int grp = (kc >> 3) * 8;
                int c0 = kc & 7;   // 0 or 4
                int p0 = grp + ((c0 < 4) ? 2 * c0 : 2 * (c0 - 4) + 1);
                R[p0]     = to_tf32(o0);
                R[p0 + 2] = to_tf32(o1);
                R[p0 + 4] = to_tf32(o2);
                R[p0 + 6] = to_tf32(o3);
            }
        }
        __syncthreads();

        // ================= pass 2: Y @ W2 =================
        #pragma unroll
        for (int j = 0; j < 8; ++j) {
            acc[j][0] = 0.f; acc[j][1] = 0.f; acc[j][2] = 0.f; acc[j][3] = 0.f;
        }
        #pragma unroll
        for (int s = 0; s < 16; ++s) {
            const float* xp = &Xs[(wr + fr) * 136 + s * 8 + c2];
            float2 alo = *(const float2*)xp;
            float2 ahi = *(const float2*)(xp + 8 * 136);
            uint32_t a0 = __float_as_uint(alo.x), a2 = __float_as_uint(alo.y);
            uint32_t a1 = __float_as_uint(ahi.x), a3 = __float_as_uint(ahi.y);
            const float* wp = &Ws2[((s * 128) + wc + fr) * 8 + c2];
            #pragma unroll
            for (int j = 0; j < 8; ++j) {
                float2 bvj = *(const float2*)(wp + j * 64);
                uint32_t b0 = __float_as_uint(bvj.x), bq = __float_as_uint(bvj.y);
                asm volatile(
                    "mma.sync.aligned.m16n8k8.row.col.f32.tf32.tf32.f32 "
                    "{%0,%1,%2,%3}, {%4,%5,%6,%7}, {%8,%9}, {%0,%1,%2,%3};"
                    : "+f"(acc[j][0]), "+f"(acc[j][1]), "+f"(acc[j][2]), "+f"(acc[j][3])
                    : "r"(a0), "r"(a1), "r"(a2), "r"(a3), "r"(b0), "r"(bq));
            }
        }
        __syncthreads();
        #pragma unroll
        for (int j = 0; j < 8; ++j) {
            int n = wc + j * 8 + c2;
            *(float2*)&Xs[(wr + fr) * 136 + n]     = make_float2(acc[j][0], acc[j][1]);
            *(float2*)&Xs[(wr + fr + 8) * 136 + n] = make_float2(acc[j][2], acc[j][3]);
        }
        __syncthreads();

        // ---- LN2 + ReLU -> gmem ----
        {
            float4 b4 = ((const float4*)bs2)[lane];
            float4 g4 = ((const float4*)gs2)[lane];
            float4 e4 = ((const float4*)es2)[lane];
            #pragma unroll
            for (int rr = 0; rr < 8; ++rr) {
                int lrow = warp * 8 + rr;
                int grow = rowBlk + lrow;
                float4 aa = *(const float4*)&Xs[lrow * 136 + lane * 4];
                float a0 = aa.x + b4.x, a1 = aa.y + b4.y, a2 = aa.z + b4.z, a3 = aa.w + b4.w;
                float s = a0 + a1 + a2 + a3;
                float q = a0 * a0 + a1 * a1 + a2 * a2 + a3 * a3;
                #pragma unroll
                for (int off = 16; off > 0; off >>= 1) {
                    s += __shfl_xor_sync(0xFFFFFFFFu, s, off);
                    q += __shfl_xor_sync(0xFFFFFFFFu, q, off);
                }
                float mu   = s * (1.0f / 128.0f);
                float var  = q * (1.0f / 128.0f) - mu * mu;
                float rstd = rsqrtf(var + 1e-5f);
                float4 o;
                o.x = fmaxf(0.f, (a0 - mu) * rstd * g4.x + e4.x);
                o.y = fmaxf(0.f, (a1 - mu) * rstd * g4.y + e4.y);
                o.z = fmaxf(0.f, (a2 - mu) * rstd * g4.z + e4.z);
                o.w = fmaxf(0.f, (a3 - mu) * rstd * g4.w + e4.w);
                if (grow < nrows)
                    *(float4*)(out + (size_t)grow * DF + lane * 4) = o;
            }
        }
        __syncthreads();
    }
}

// ---------------------------------------------------------------------------
__global__ void pool_kernel(const float* __restrict__ h, const int* __restrict__ gid,
                            float* __restrict__ pool, int N) {
    int c  = threadIdx.x;
    int n0 = blockIdx.x * 128;
    if (n0 >= N) return;
    int curg = __ldg(gid + n0);
    float acc = 0.f;
    #pragma unroll 4
    for (int i = 0; i < 128; ++i) {
        int n = n0 + i;
        if (n >= N) break;
        int g = __ldg(gid + n);
        if (g != curg) {
            atomicAdd(&pool[(size_t)curg * DF + c], acc);
            acc = 0.f;
            curg = g;
        }
        acc += __ldg(h + (size_t)n * DF + c);
    }
    atomicAdd(&pool[(size_t)curg * DF + c], acc);
}

// ---------------------------------------------------------------------------
__global__ void head_kernel(const float* __restrict__ pool, const float* __restrict__ desc,
                            const float* __restrict__ fc1W, const float* __restrict__ fc1b,
                            const float* __restrict__ n1g, const float* __restrict__ n1b,
                            const float* __restrict__ fc2W, const float* __restrict__ fc2b,
                            float* __restrict__ out, int X, int C) {
    int g = blockIdx.x;
    int t = threadIdx.x;
    int warp = t >> 5, lane = t & 31;

    __shared__ float xin[DF + 64];
    __shared__ float ss[4], qq[4];

    xin[t] = pool[(size_t)g * DF + t];
    if (t < X) xin[DF + t] = desc[(size_t)g * X + t];
    __syncthreads();

    int K = DF + X;
    float acc = fc1b[t];
    for (int k = 0; k < K; ++k)
        acc = fmaf(xin[k], __ldg(fc1W + (size_t)k * DF + t), acc);

    float s = acc, q = acc * acc;
    #pragma unroll
    for (int off = 16; off > 0; off >>= 1) {
        s += __shfl_xor_sync(0xFFFFFFFFu, s, off);
        q += __shfl_xor_sync(0xFFFFFFFFu, q, off);
    }
    if (lane == 0) { ss[warp] = s; qq[warp] = q; }
    __syncthreads();
    s = ss[0] + ss[1] + ss[2] + ss[3];
    q = qq[0] + qq[1] + qq[2] + qq[3];
    float mu   = s * (1.0f / 128.0f);
    float var  = q * (1.0f / 128.0f) - mu * mu;
    float rstd = rsqrtf(var + 1e-5f);
    float y = fmaxf(0.f, (acc - mu) * rstd * n1g[t] + n1b[t]);

    for (int c = 0; c < C; ++c) {
        float p = y * __ldg(fc2W + (size_t)t * C + c);
        #pragma unroll
        for (int off = 16; off > 0; off >>= 1)
            p += __shfl_xor_sync(0xFFFFFFFFu, p, off);
        __syncthreads();
        if (lane == 0) ss[warp] = p;
        __syncthreads();
        if (t == 0) out[(size_t)g * C + c] = ss[0] + ss[1] + ss[2] + ss[3] + fc2b[c];
    }
}

// ---------------------------------------------------------------------------
extern "C" void kernel_launch(void* const* d_in, const int* in_sizes, int n_in,
                              void* d_out, int out_size) {
    const float* h    = (const float*)d_in[0];
    const float* desc = (const float*)d_in[1];
    const int*   src  = (const int*)d_in[2];
    const int*   dst  = (const int*)d_in[3];
    const int*   gid  = (const int*)d_in[4];
    const float* W1   = (const float*)d_in[5];
    const float* b1   = (const float*)d_in[6];
    const float* g1   = (const float*)d_in[7];
    const float* be1  = (const float*)d_in[8];
    const float* W2   = (const float*)d_in[9];
    const float* b2   = (const float*)d_in[10];
    const float* eps  = (const float*)d_in[11];
    const float* ng   = (const float*)d_in[12];
    const float* nb   = (const float*)d_in[13];
    const float* fc1W = (const float*)d_in[14];
    const float* fc1b = (const float*)d_in[15];
    const float* n1g  = (const float*)d_in[16];
    const float* n1b  = (const float*)d_in[17];
    const float* fc2W = (const float*)d_in[18];
    const float* fc2b = (const float*)d_in[19];
    float* out = (float*)d_out;

    int N = in_sizes[0] / DF;
    int E = in_sizes[2];
    int L = in_sizes[11];
    int X = in_sizes[14] / DF - DF;
    if (X <= 0) X = 16;
    int G = in_sizes[1] / X;
    int C = in_sizes[18] / DF;
    if (C <= 0) C = 1;
    if (N > NMAX) N = NMAX;
    if (G > GMAX) G = GMAX;
    if (E > EMAX) E = EMAX;

    float *bufA, *bufC, *pool;
    int *degp, *rowptr, *cursor, *csrc, *bsum;
    cudaGetSymbolAddress((void**)&bufA, g_bufA);
    cudaGetSymbolAddress((void**)&bufC, g_bufC);
    cudaGetSymbolAddress((void**)&pool, g_pool);
    cudaGetSymbolAddress((void**)&degp, g_deg);
    cudaGetSymbolAddress((void**)&rowptr, g_rowptr);
    cudaGetSymbolAddress((void**)&cursor, g_cursor);
    cudaGetSymbolAddress((void**)&csrc, g_csrc);
    cudaGetSymbolAddress((void**)&bsum, g_bsum);

    const int SMEM_BYTES = (2 * 16384 + 17408 + 6 * DF) * sizeof(float); // 203,776
    cudaFuncSetAttribute(layer_fused,
                         cudaFuncAttributeMaxDynamicSharedMemorySize, SMEM_BYTES);

    // --- CSR build (once per launch) ---
    int nb_scan = (N + 1023) / 1024;
    cudaMemsetAsync(degp, 0, (size_t)N * sizeof(int));
    deg_kernel<<<(E + 255) / 256, 256>>>(dst, degp, E);
    scan1_kernel<<<nb_scan, 1024>>>(degp, rowptr, bsum, N);
    scan2_kernel<<<1, 32>>>(bsum, nb_scan);
    scan3_kernel<<<nb_scan, 1024>>>(rowptr, bsum, N, E);
    cudaMemcpyAsync(cursor, rowptr, (size_t)N * sizeof(int), cudaMemcpyDeviceToDevice);
    scatter_kernel<<<(E + 255) / 256, 256>>>(src, dst, cursor, csrc, E);

    int ntiles = (N + 127) / 128;
    int fgrid = ntiles < 148 ? ntiles : 148;
    int agg_grid = (N * 32 + 255) / 256;

    const float* hcur = h;
    for (int l = 0; l < L; ++l) {
        agg_kernel<<<agg_grid, 256>>>(hcur, rowptr, csrc, bufA, N);
        layer_fused<<<fgrid, 512, SMEM_BYTES>>>(
            bufA, hcur, eps, l,
            W1 + (size_t)l * DF * DF, b1 + (size_t)l * DF,
            g1 + (size_t)l * DF, be1 + (size_t)l * DF,
            W2 + (size_t)l * DF * DF, b2 + (size_t)l * DF,
            ng + (size_t)l * DF, nb + (size_t)l * DF,
            bufC, N, ntiles);
        hcur = bufC;
    }

    cudaMemsetAsync(pool, 0, (size_t)G * DF * sizeof(float));
    pool_kernel<<<(N + 127) / 128, 128>>>(hcur, gid, pool, N);
    head_kernel<<<G, 128>>>(pool, desc, fc1W, fc1b, n1g, n1b, fc2W, fc2b, out, X, C);
}